// round 11
// baseline (speedup 1.0000x reference)
#include <cuda_runtime.h>
#include <cuda_fp16.h>
#include <stdint.h>
#include <math.h>

#define SEQ     4096
#define DIM     1024
#define NHEADS  16
#define NKV     4
#define HD      64
#define KVDIM   256
#define LOG2E   1.44269504088896f

// ---------------------------------------------------------------------------
// Scratch (device globals; cudaMalloc forbidden) — fp16
// ---------------------------------------------------------------------------
__device__ __half g_qh[SEQ * DIM];
__device__ __half g_kh[SEQ * KVDIM];
__device__ __half g_vh[SEQ * KVDIM];
__device__ __half g_ah[SEQ * DIM];
__device__ __half g_xh[SEQ * DIM];
__device__ __half g_wqh[DIM * DIM];
__device__ __half g_wkh[KVDIM * DIM];
__device__ __half g_wvh[KVDIM * DIM];
__device__ __half g_woh[DIM * DIM];

// ---------------------------------------------------------------------------
// Helpers
// ---------------------------------------------------------------------------
__device__ __forceinline__ uint32_t pack_h2(float a, float b) {
    __half2 h = __floats2half2_rn(a, b);
    return *(uint32_t*)&h;
}
__device__ __forceinline__ uint32_t smem_u32(const void* p) {
    uint32_t a;
    asm("{ .reg .u64 t; cvta.to.shared.u64 t, %1; cvt.u32.u64 %0, t; }"
        : "=r"(a) : "l"(p));
    return a;
}
__device__ __forceinline__ void mma_f16(float c[4], const uint32_t a[4],
                                        const uint32_t b[2]) {
    asm volatile(
        "mma.sync.aligned.m16n8k16.row.col.f32.f16.f16.f32 "
        "{%0,%1,%2,%3},{%4,%5,%6,%7},{%8,%9},{%0,%1,%2,%3};"
        : "+f"(c[0]), "+f"(c[1]), "+f"(c[2]), "+f"(c[3])
        : "r"(a[0]), "r"(a[1]), "r"(a[2]), "r"(a[3]), "r"(b[0]), "r"(b[1]));
}
__device__ __forceinline__ void ldsm_x4_trans(uint32_t& r0, uint32_t& r1,
                                              uint32_t& r2, uint32_t& r3,
                                              uint32_t addr) {
    asm volatile(
        "ldmatrix.sync.aligned.m8n8.x4.trans.shared.b16 {%0,%1,%2,%3}, [%4];"
        : "=r"(r0), "=r"(r1), "=r"(r2), "=r"(r3) : "r"(addr));
}
__device__ __forceinline__ void cp16(uint32_t dst, const void* src) {
    asm volatile("cp.async.cg.shared.global [%0], [%1], 16;"
                 :: "r"(dst), "l"(src));
}
#define CP_COMMIT() asm volatile("cp.async.commit_group;" ::: "memory")
template <int N>
__device__ __forceinline__ void cp_wait() {
    asm volatile("cp.async.wait_group %0;" :: "n"(N) : "memory");
}

// ---------------------------------------------------------------------------
// fp32 -> fp16 conversion prepass
// ---------------------------------------------------------------------------
__global__ void cvt_h(const float4* __restrict__ in, uint2* __restrict__ out,
                      int n4) {
    int i = blockIdx.x * blockDim.x + threadIdx.x;
    if (i >= n4) return;
    float4 v = in[i];
    out[i] = make_uint2(pack_h2(v.x, v.y), pack_h2(v.z, v.w));
}

// ---------------------------------------------------------------------------
// f16 GEMM: C[M,N] = alpha * A[M,K] @ B[N,K]^T, optional fused RoPE epilogue.
// A, B fp16 row-major. C half or float. cp.async double-buffered mainloop.
// BM=128, BN=64, BK=32, 256 threads (8 warps 4m x 2n), warp tile 32x32.
// ---------------------------------------------------------------------------
#define GAP 40

template <bool ROPE, bool CHALF>
__global__ __launch_bounds__(256) void gemm_h(const __half* __restrict__ A,
                                              const __half* __restrict__ B,
                                              void* __restrict__ Cp,
                                              int M, int N, int K,
                                              const float* __restrict__ cosb,
                                              const float* __restrict__ sinb,
                                              float alpha) {
    __shared__ __align__(16) __half As[2][128 * GAP];
    __shared__ __align__(16) __half Bs[2][64 * GAP];

    const int tid = threadIdx.x;
    const int wid = tid >> 5;
    const int lane = tid & 31;
    const int g = lane >> 2;
    const int c = lane & 3;
    const int wm = wid >> 1;
    const int wn = wid & 1;
    const int row0 = blockIdx.y * 128;
    const int col0 = blockIdx.x * 64;

    const uint32_t abase = smem_u32(&As[0][0]);
    const uint32_t bbase = smem_u32(&Bs[0][0]);

    auto load = [&](int i, int st) {
        int k0 = i * 32;
        uint32_t ab = abase + (uint32_t)st * (128 * GAP * 2);
        uint32_t bb = bbase + (uint32_t)st * (64 * GAP * 2);
#pragma unroll
        for (int j = 0; j < 2; j++) {
            int lin = tid + 256 * j;
            int r  = lin >> 2;
            int k8 = (lin & 3) << 3;
            cp16(ab + (uint32_t)(r * GAP + k8) * 2,
                 &A[(size_t)(row0 + r) * K + k0 + k8]);
        }
        {
            int r  = tid >> 2;
            int k8 = (tid & 3) << 3;
            cp16(bb + (uint32_t)(r * GAP + k8) * 2,
                 &B[(size_t)(col0 + r) * K + k0 + k8]);
        }
        CP_COMMIT();
    };

    float acc[2][4][4] = {};
    const int NI = K / 32;
    load(0, 0);

    for (int i = 0; i < NI; i++) {
        const int st = i & 1;
        if (i + 1 < NI) { load(i + 1, st ^ 1); cp_wait<1>(); }
        else           { cp_wait<0>(); }
        __syncthreads();

        const __half* Asb = As[st];
        const __half* Bsb = Bs[st];
#pragma unroll
        for (int kk = 0; kk < 2; kk++) {
            uint32_t a[2][4];
#pragma unroll
            for (int mt = 0; mt < 2; mt++) {
                int mb = wm * 32 + mt * 16;
                a[mt][0] = *(uint32_t*)&Asb[(mb + g)     * GAP + kk * 16 + 2 * c];
                a[mt][1] = *(uint32_t*)&Asb[(mb + g + 8) * GAP + kk * 16 + 2 * c];
                a[mt][2] = *(uint32_t*)&Asb[(mb + g)     * GAP + kk * 16 + 2 * c + 8];
                a[mt][3] = *(uint32_t*)&Asb[(mb + g + 8) * GAP + kk * 16 + 2 * c + 8];
            }
#pragma unroll
            for (int nt = 0; nt < 4; nt++) {
                int nb = wn * 32 + nt * 8;
                uint32_t b[2];
                b[0] = *(uint32_t*)&Bsb[(nb + g) * GAP + kk * 16 + 2 * c];
                b[1] = *(uint32_t*)&Bsb[(nb + g) * GAP + kk * 16 + 2 * c + 8];
#pragma unroll
                for (int mt = 0; mt < 2; mt++)
                    mma_f16(acc[mt][nt], a[mt], b);
            }
        }
        __syncthreads();
    }

    // Epilogue: optional scale + RoPE rotation, then store.
#pragma unroll
    for (int mt = 0; mt < 2; mt++) {
#pragma unroll
        for (int nt = 0; nt < 4; nt++) {
            int r = row0 + wm * 32 + mt * 16 + g;
            int col = col0 + wn * 32 + nt * 8 + 2 * c;
            float v0 = acc[mt][nt][0] * alpha;
            float v1 = acc[mt][nt][1] * alpha;
            float v2 = acc[mt][nt][2] * alpha;
            float v3 = acc[mt][nt][3] * alpha;
            if (ROPE) {
                int i = (col & 63) >> 1;
                float c0 = cosb[r * 32 + i],        s0 = sinb[r * 32 + i];
                float c1 = cosb[(r + 8) * 32 + i],  s1 = sinb[(r + 8) * 32 + i];
                float t0 = v0 * c0 - v1 * s0;
                float t1 = v0 * s0 + v1 * c0;
                float t2 = v2 * c1 - v3 * s1;
                float t3 = v2 * s1 + v3 * c1;
                v0 = t0; v1 = t1; v2 = t2; v3 = t3;
            }
            if (CHALF) {
                __half* C = (__half*)Cp;
                *(uint32_t*)&C[(size_t)r * N + col]       = pack_h2(v0, v1);
                *(uint32_t*)&C[(size_t)(r + 8) * N + col] = pack_h2(v2, v3);
            } else {
                float* C = (float*)Cp;
                *(float2*)&C[(size_t)r * N + col]       = make_float2(v0, v1);
                *(float2*)&C[(size_t)(r + 8) * N + col] = make_float2(v2, v3);
            }
        }
    }
}

// ---------------------------------------------------------------------------
// Flash attention, f16 m16n8k16, causal, GQA. fp16 in/out.
// Q is pre-scaled by log2(e)/8 in projection, so softmax uses exp2f (bare
// MUFU.EX2). 256 threads; q-tile 128, k-tile 64; Q frags in registers; P in
// registers; K/V double-buffered cp.async. minBlocks=3 to lift occupancy.
// ---------------------------------------------------------------------------
#define FP 72
#define FL_QS 0
#define FL_K0 (128 * FP)
#define FL_V0 (FL_K0 + 64 * FP)
#define KVBUF (128 * FP)
#define FLASH_SMEM ((128 * FP + 2 * KVBUF) * 2)

extern __shared__ __half fsm[];

__global__ __launch_bounds__(256, 3) void flash_f16(const __half* __restrict__ Q,
                                                    const __half* __restrict__ K,
                                                    const __half* __restrict__ V,
                                                    __half* __restrict__ O) {
    __half* Qs = fsm + FL_QS;

    const int qt = gridDim.x - 1 - blockIdx.x;
    const int h  = blockIdx.y;
    const int kvh = h >> 2;
    const int tid = threadIdx.x;
    const int w = tid >> 5;
    const int lane = tid & 31;
    const int g = lane >> 2;
    const int c = lane & 3;
    const int q0 = qt * 128;
    const int qb = w * 16;

    const uint32_t sbase = smem_u32(fsm);
    const int lm_row = lane & 15;
    const int lm_cs  = (lane >> 4) & 1;

    const int NT = 2 * qt + 2;

    auto load_kv = [&](int kt, int buf) {
        const int k0 = kt * 64;
        uint32_t kb = sbase + (uint32_t)(FL_K0 + buf * KVBUF) * 2;
        uint32_t vb = sbase + (uint32_t)(FL_V0 + buf * KVBUF) * 2;
#pragma unroll
        for (int i = 0; i < 2; i++) {
            int lin = tid + 256 * i;
            int r  = lin >> 3;
            int d8 = (lin & 7) << 3;
            uint32_t off = (uint32_t)(r * FP + d8) * 2;
            cp16(kb + off, &K[(size_t)(k0 + r) * KVDIM + kvh * HD + d8]);
            cp16(vb + off, &V[(size_t)(k0 + r) * KVDIM + kvh * HD + d8]);
        }
        CP_COMMIT();
    };

#pragma unroll
    for (int i = 0; i < 4; i++) {
        int lin = tid + 256 * i;
        int r  = lin >> 3;
        int d8 = (lin & 7) << 3;
        *(uint4*)&Qs[r * FP + d8] =
            *(const uint4*)&Q[(size_t)(q0 + r) * DIM + h * HD + d8];
    }
    load_kv(0, 0);
    __syncthreads();

    uint32_t qf[4][4];
#pragma unroll
    for (int kk = 0; kk < 4; kk++) {
        qf[kk][0] = *(uint32_t*)&Qs[(qb + g)     * FP + kk * 16 + 2 * c];
        qf[kk][1] = *(uint32_t*)&Qs[(qb + g + 8) * FP + kk * 16 + 2 * c];
        qf[kk][2] = *(uint32_t*)&Qs[(qb + g)     * FP + kk * 16 + 2 * c + 8];
        qf[kk][3] = *(uint32_t*)&Qs[(qb + g + 8) * FP + kk * 16 + 2 * c + 8];
    }

    float m0 = -1e30f, m1 = -1e30f, l0 = 0.f, l1 = 0.f;
    float oacc[8][4] = {};

    for (int kt = 0; kt < NT; kt++) {
        const int buf = kt & 1;
        const int k0 = kt * 64;
        cp_wait<0>();
        __syncthreads();

        if (kt + 1 < NT) load_kv(kt + 1, buf ^ 1);

        if (k0 > q0 + qb + 15) continue;

        __half* Ks = fsm + FL_K0 + buf * KVBUF;
        const uint32_t vbyte = sbase + (uint32_t)(FL_V0 + buf * KVBUF) * 2;

        // S = Q K^T (S already in log2 domain: Q pre-scaled by log2e/8).
        float s[8][4] = {};
#pragma unroll
        for (int kk = 0; kk < 4; kk++) {
#pragma unroll
            for (int nt = 0; nt < 8; nt++) {
                uint32_t b[2];
                b[0] = *(uint32_t*)&Ks[(nt * 8 + g) * FP + kk * 16 + 2 * c];
                b[1] = *(uint32_t*)&Ks[(nt * 8 + g) * FP + kk * 16 + 2 * c + 8];
                mma_f16(s[nt], qf[kk], b);
            }
        }

        if (kt >= 2 * qt) {
            int r0 = q0 + qb + g, r1 = r0 + 8;
#pragma unroll
            for (int nt = 0; nt < 8; nt++) {
                int col = k0 + nt * 8 + 2 * c;
                if (col     > r0) s[nt][0] = -1e30f;
                if (col + 1 > r0) s[nt][1] = -1e30f;
                if (col     > r1) s[nt][2] = -1e30f;
                if (col + 1 > r1) s[nt][3] = -1e30f;
            }
        }

        // Online softmax in exp2 domain.
        float mx0 = -1e30f, mx1 = -1e30f;
#pragma unroll
        for (int nt = 0; nt < 8; nt++) {
            mx0 = fmaxf(mx0, fmaxf(s[nt][0], s[nt][1]));
            mx1 = fmaxf(mx1, fmaxf(s[nt][2], s[nt][3]));
        }
        mx0 = fmaxf(mx0, __shfl_xor_sync(0xffffffffu, mx0, 1));
        mx0 = fmaxf(mx0, __shfl_xor_sync(0xffffffffu, mx0, 2));
        mx1 = fmaxf(mx1, __shfl_xor_sync(0xffffffffu, mx1, 1));
        mx1 = fmaxf(mx1, __shfl_xor_sync(0xffffffffu, mx1, 2));

        float mn0 = fmaxf(m0, mx0), mn1 = fmaxf(m1, mx1);
        float al0 = exp2f(m0 - mn0), al1 = exp2f(m1 - mn1);
        float sum0 = 0.f, sum1 = 0.f;
#pragma unroll
        for (int nt = 0; nt < 8; nt++) {
            s[nt][0] = exp2f(s[nt][0] - mn0);
            s[nt][1] = exp2f(s[nt][1] - mn0);
            s[nt][2] = exp2f(s[nt][2] - mn1);
            s[nt][3] = exp2f(s[nt][3] - mn1);
            sum0 += s[nt][0] + s[nt][1];
            sum1 += s[nt][2] + s[nt][3];
        }
        sum0 += __shfl_xor_sync(0xffffffffu, sum0, 1);
        sum0 += __shfl_xor_sync(0xffffffffu, sum0, 2);
        sum1 += __shfl_xor_sync(0xffffffffu, sum1, 1);
        sum1 += __shfl_xor_sync(0xffffffffu, sum1, 2);
        l0 = l0 * al0 + sum0;  m0 = mn0;
        l1 = l1 * al1 + sum1;  m1 = mn1;
#pragma unroll
        for (int nt = 0; nt < 8; nt++) {
            oacc[nt][0] *= al0; oacc[nt][1] *= al0;
            oacc[nt][2] *= al1; oacc[nt][3] *= al1;
        }

        // O += P V; P A-fragments direct from S C-fragments.
#pragma unroll
        for (int kk = 0; kk < 4; kk++) {
            uint32_t a[4];
            a[0] = pack_h2(s[2 * kk][0],     s[2 * kk][1]);
            a[1] = pack_h2(s[2 * kk][2],     s[2 * kk][3]);
            a[2] = pack_h2(s[2 * kk + 1][0], s[2 * kk + 1][1]);
            a[3] = pack_h2(s[2 * kk + 1][2], s[2 * kk + 1][3]);
#pragma unroll
            for (int ntp = 0; ntp < 4; ntp++) {
                uint32_t addr = vbyte +
                    (uint32_t)(kk * 16 + lm_row) * (FP * 2) +
                    (uint32_t)(16 * ntp + 8 * lm_cs) * 2;
                uint32_t b0, b1, b2, b3;
                ldsm_x4_trans(b0, b1, b2, b3, addr);
                uint32_t blo[2] = {b0, b1}, bhi[2] = {b2, b3};
                mma_f16(oacc[2 * ntp],     a, blo);
                mma_f16(oacc[2 * ntp + 1], a, bhi);
            }
        }
    }

    float inv0 = 1.f / l0, inv1 = 1.f / l1;
    int r0 = q0 + qb + g;
#pragma unroll
    for (int nt = 0; nt < 8; nt++) {
        int col = h * HD + nt * 8 + 2 * c;
        *(uint32_t*)&O[(size_t)r0 * DIM + col] =
            pack_h2(oacc[nt][0] * inv0, oacc[nt][1] * inv0);
        *(uint32_t*)&O[(size_t)(r0 + 8) * DIM + col] =
            pack_h2(oacc[nt][2] * inv1, oacc[nt][3] * inv1);
    }
}

// ---------------------------------------------------------------------------
// Launch
// ---------------------------------------------------------------------------
extern "C" void kernel_launch(void* const* d_in, const int* in_sizes, int n_in,
                              void* d_out, int out_size) {
    const float* x  = (const float*)d_in[0];
    const float* fc = (const float*)d_in[1];
    const float* fs = (const float*)d_in[2];
    const float* wq = (const float*)d_in[3];
    const float* wk = (const float*)d_in[4];
    const float* wv = (const float*)d_in[5];
    const float* wo = (const float*)d_in[6];
    float* out = (float*)d_out;

    static __half *pq = nullptr, *pk, *pv, *pa, *px, *pwq, *pwk, *pwv, *pwo;
    if (!pq) {
        cudaGetSymbolAddress((void**)&pq,  g_qh);
        cudaGetSymbolAddress((void**)&pk,  g_kh);
        cudaGetSymbolAddress((void**)&pv,  g_vh);
        cudaGetSymbolAddress((void**)&pa,  g_ah);
        cudaGetSymbolAddress((void**)&px,  g_xh);
        cudaGetSymbolAddress((void**)&pwq, g_wqh);
        cudaGetSymbolAddress((void**)&pwk, g_wkh);
        cudaGetSymbolAddress((void**)&pwv, g_wvh);
        cudaGetSymbolAddress((void**)&pwo, g_woh);
        cudaFuncSetAttribute(flash_f16,
                             cudaFuncAttributeMaxDynamicSharedMemorySize,
                             FLASH_SMEM);
    }

    auto cvt = [&](const float* src, __half* dst, int n) {
        cvt_h<<<(n / 4 + 255) / 256, 256>>>((const float4*)src, (uint2*)dst,
                                            n / 4);
    };
    cvt(x,  px,  SEQ * DIM);
    cvt(wq, pwq, DIM * DIM);
    cvt(wk, pwk, KVDIM * DIM);
    cvt(wv, pwv, KVDIM * DIM);
    cvt(wo, pwo, DIM * DIM);

    dim3 blk(256);
    // Q proj: rope + (log2e / sqrt(64)) scale fused, half out.
    gemm_h<true, true><<<dim3(DIM / 64, SEQ / 128), blk>>>(
        px, pwq, pq, SEQ, DIM, DIM, fc, fs, 0.125f * LOG2E);
    // K proj: rope fused, half out.
    gemm_h<true, true><<<dim3(KVDIM / 64, SEQ / 128), blk>>>(
        px, pwk, pk, SEQ, KVDIM, DIM, fc, fs, 1.0f);
    // V proj: half out.
    gemm_h<false, true><<<dim3(KVDIM / 64, SEQ / 128), blk>>>(
        px, pwv, pv, SEQ, KVDIM, DIM, nullptr, nullptr, 1.0f);

    // Flash attention.
    flash_f16<<<dim3(SEQ / 128, NHEADS), blk, FLASH_SMEM>>>(pq, pk, pv, pa);

    // O proj: half operands, float out.
    gemm_h<false, false><<<dim3(DIM / 64, SEQ / 128), blk>>>(
        pa, pwo, out, SEQ, DIM, DIM, nullptr, nullptr, 1.0f);
}

// round 12
// speedup vs baseline: 1.2301x; 1.2301x over previous
#include <cuda_runtime.h>
#include <cuda_fp16.h>
#include <stdint.h>
#include <math.h>

#define SEQ     4096
#define DIM     1024
#define NHEADS  16
#define NKV     4
#define HD      64
#define KVDIM   256
#define LOG2E   1.44269504088896f

// ---------------------------------------------------------------------------
// Scratch (device globals; cudaMalloc forbidden) — fp16
// ---------------------------------------------------------------------------
__device__ __half g_qh[SEQ * DIM];
__device__ __half g_kh[SEQ * KVDIM];
__device__ __half g_vh[SEQ * KVDIM];
__device__ __half g_ah[SEQ * DIM];
__device__ __half g_xh[SEQ * DIM];
__device__ __half g_wqh[DIM * DIM];
__device__ __half g_wkh[KVDIM * DIM];
__device__ __half g_wvh[KVDIM * DIM];
__device__ __half g_woh[DIM * DIM];

// ---------------------------------------------------------------------------
// Helpers
// ---------------------------------------------------------------------------
__device__ __forceinline__ uint32_t pack_h2(float a, float b) {
    __half2 h = __floats2half2_rn(a, b);
    return *(uint32_t*)&h;
}
__device__ __forceinline__ uint32_t smem_u32(const void* p) {
    uint32_t a;
    asm("{ .reg .u64 t; cvta.to.shared.u64 t, %1; cvt.u32.u64 %0, t; }"
        : "=r"(a) : "l"(p));
    return a;
}
__device__ __forceinline__ void mma_f16(float c[4], const uint32_t a[4],
                                        const uint32_t b[2]) {
    asm volatile(
        "mma.sync.aligned.m16n8k16.row.col.f32.f16.f16.f32 "
        "{%0,%1,%2,%3},{%4,%5,%6,%7},{%8,%9},{%0,%1,%2,%3};"
        : "+f"(c[0]), "+f"(c[1]), "+f"(c[2]), "+f"(c[3])
        : "r"(a[0]), "r"(a[1]), "r"(a[2]), "r"(a[3]), "r"(b[0]), "r"(b[1]));
}
__device__ __forceinline__ void ldsm_x4_trans(uint32_t& r0, uint32_t& r1,
                                              uint32_t& r2, uint32_t& r3,
                                              uint32_t addr) {
    asm volatile(
        "ldmatrix.sync.aligned.m8n8.x4.trans.shared.b16 {%0,%1,%2,%3}, [%4];"
        : "=r"(r0), "=r"(r1), "=r"(r2), "=r"(r3) : "r"(addr));
}
__device__ __forceinline__ void cp16(uint32_t dst, const void* src) {
    asm volatile("cp.async.cg.shared.global [%0], [%1], 16;"
                 :: "r"(dst), "l"(src));
}
#define CP_COMMIT() asm volatile("cp.async.commit_group;" ::: "memory")
template <int N>
__device__ __forceinline__ void cp_wait() {
    asm volatile("cp.async.wait_group %0;" :: "n"(N) : "memory");
}

// ---------------------------------------------------------------------------
// fp32 -> fp16 conversion prepass
// ---------------------------------------------------------------------------
__global__ void cvt_h(const float4* __restrict__ in, uint2* __restrict__ out,
                      int n4) {
    int i = blockIdx.x * blockDim.x + threadIdx.x;
    if (i >= n4) return;
    float4 v = in[i];
    out[i] = make_uint2(pack_h2(v.x, v.y), pack_h2(v.z, v.w));
}

// ---------------------------------------------------------------------------
// f16 GEMM: C[M,N] = alpha * A[M,K] @ B[N,K]^T, optional fused RoPE epilogue.
// A, B fp16 row-major. C half or float. cp.async double-buffered mainloop.
// BM=128, BN=64, BK=32, 256 threads (8 warps 4m x 2n), warp tile 32x32.
// ---------------------------------------------------------------------------
#define GAP 40

template <bool ROPE, bool CHALF>
__global__ __launch_bounds__(256) void gemm_h(const __half* __restrict__ A,
                                              const __half* __restrict__ B,
                                              void* __restrict__ Cp,
                                              int M, int N, int K,
                                              const float* __restrict__ cosb,
                                              const float* __restrict__ sinb,
                                              float alpha) {
    __shared__ __align__(16) __half As[2][128 * GAP];
    __shared__ __align__(16) __half Bs[2][64 * GAP];

    const int tid = threadIdx.x;
    const int wid = tid >> 5;
    const int lane = tid & 31;
    const int g = lane >> 2;
    const int c = lane & 3;
    const int wm = wid >> 1;
    const int wn = wid & 1;
    const int row0 = blockIdx.y * 128;
    const int col0 = blockIdx.x * 64;

    const uint32_t abase = smem_u32(&As[0][0]);
    const uint32_t bbase = smem_u32(&Bs[0][0]);

    auto load = [&](int i, int st) {
        int k0 = i * 32;
        uint32_t ab = abase + (uint32_t)st * (128 * GAP * 2);
        uint32_t bb = bbase + (uint32_t)st * (64 * GAP * 2);
#pragma unroll
        for (int j = 0; j < 2; j++) {
            int lin = tid + 256 * j;
            int r  = lin >> 2;
            int k8 = (lin & 3) << 3;
            cp16(ab + (uint32_t)(r * GAP + k8) * 2,
                 &A[(size_t)(row0 + r) * K + k0 + k8]);
        }
        {
            int r  = tid >> 2;
            int k8 = (tid & 3) << 3;
            cp16(bb + (uint32_t)(r * GAP + k8) * 2,
                 &B[(size_t)(col0 + r) * K + k0 + k8]);
        }
        CP_COMMIT();
    };

    float acc[2][4][4] = {};
    const int NI = K / 32;
    load(0, 0);

    for (int i = 0; i < NI; i++) {
        const int st = i & 1;
        if (i + 1 < NI) { load(i + 1, st ^ 1); cp_wait<1>(); }
        else           { cp_wait<0>(); }
        __syncthreads();

        const __half* Asb = As[st];
        const __half* Bsb = Bs[st];
#pragma unroll
        for (int kk = 0; kk < 2; kk++) {
            uint32_t a[2][4];
#pragma unroll
            for (int mt = 0; mt < 2; mt++) {
                int mb = wm * 32 + mt * 16;
                a[mt][0] = *(uint32_t*)&Asb[(mb + g)     * GAP + kk * 16 + 2 * c];
                a[mt][1] = *(uint32_t*)&Asb[(mb + g + 8) * GAP + kk * 16 + 2 * c];
                a[mt][2] = *(uint32_t*)&Asb[(mb + g)     * GAP + kk * 16 + 2 * c + 8];
                a[mt][3] = *(uint32_t*)&Asb[(mb + g + 8) * GAP + kk * 16 + 2 * c + 8];
            }
#pragma unroll
            for (int nt = 0; nt < 4; nt++) {
                int nb = wn * 32 + nt * 8;
                uint32_t b[2];
                b[0] = *(uint32_t*)&Bsb[(nb + g) * GAP + kk * 16 + 2 * c];
                b[1] = *(uint32_t*)&Bsb[(nb + g) * GAP + kk * 16 + 2 * c + 8];
#pragma unroll
                for (int mt = 0; mt < 2; mt++)
                    mma_f16(acc[mt][nt], a[mt], b);
            }
        }
        __syncthreads();
    }

    // Epilogue: optional scale + RoPE rotation, then store.
#pragma unroll
    for (int mt = 0; mt < 2; mt++) {
#pragma unroll
        for (int nt = 0; nt < 4; nt++) {
            int r = row0 + wm * 32 + mt * 16 + g;
            int col = col0 + wn * 32 + nt * 8 + 2 * c;
            float v0 = acc[mt][nt][0] * alpha;
            float v1 = acc[mt][nt][1] * alpha;
            float v2 = acc[mt][nt][2] * alpha;
            float v3 = acc[mt][nt][3] * alpha;
            if (ROPE) {
                int i = (col & 63) >> 1;
                float c0 = cosb[r * 32 + i],        s0 = sinb[r * 32 + i];
                float c1 = cosb[(r + 8) * 32 + i],  s1 = sinb[(r + 8) * 32 + i];
                float t0 = v0 * c0 - v1 * s0;
                float t1 = v0 * s0 + v1 * c0;
                float t2 = v2 * c1 - v3 * s1;
                float t3 = v2 * s1 + v3 * c1;
                v0 = t0; v1 = t1; v2 = t2; v3 = t3;
            }
            if (CHALF) {
                __half* C = (__half*)Cp;
                *(uint32_t*)&C[(size_t)r * N + col]       = pack_h2(v0, v1);
                *(uint32_t*)&C[(size_t)(r + 8) * N + col] = pack_h2(v2, v3);
            } else {
                float* C = (float*)Cp;
                *(float2*)&C[(size_t)r * N + col]       = make_float2(v0, v1);
                *(float2*)&C[(size_t)(r + 8) * N + col] = make_float2(v2, v3);
            }
        }
    }
}

// ---------------------------------------------------------------------------
// Flash attention, f16 m16n8k16, causal, GQA. fp16 in/out.
// Q pre-scaled by log2(e)/8 in projection -> softmax uses bare exp2f.
// 256 threads; q-tile 128, k-tile 64; Q frags in registers; P in registers;
// K/V double-buffered cp.async. NO occupancy forcing (R11 showed spills cost
// more than the extra CTA gains).
// ---------------------------------------------------------------------------
#define FP 72
#define FL_QS 0
#define FL_K0 (128 * FP)
#define FL_V0 (FL_K0 + 64 * FP)
#define KVBUF (128 * FP)
#define FLASH_SMEM ((128 * FP + 2 * KVBUF) * 2)

extern __shared__ __half fsm[];

__global__ __launch_bounds__(256) void flash_f16(const __half* __restrict__ Q,
                                                 const __half* __restrict__ K,
                                                 const __half* __restrict__ V,
                                                 __half* __restrict__ O) {
    __half* Qs = fsm + FL_QS;

    const int qt = gridDim.x - 1 - blockIdx.x;
    const int h  = blockIdx.y;
    const int kvh = h >> 2;
    const int tid = threadIdx.x;
    const int w = tid >> 5;
    const int lane = tid & 31;
    const int g = lane >> 2;
    const int c = lane & 3;
    const int q0 = qt * 128;
    const int qb = w * 16;

    const uint32_t sbase = smem_u32(fsm);
    const int lm_row = lane & 15;
    const int lm_cs  = (lane >> 4) & 1;

    const int NT = 2 * qt + 2;

    auto load_kv = [&](int kt, int buf) {
        const int k0 = kt * 64;
        uint32_t kb = sbase + (uint32_t)(FL_K0 + buf * KVBUF) * 2;
        uint32_t vb = sbase + (uint32_t)(FL_V0 + buf * KVBUF) * 2;
#pragma unroll
        for (int i = 0; i < 2; i++) {
            int lin = tid + 256 * i;
            int r  = lin >> 3;
            int d8 = (lin & 7) << 3;
            uint32_t off = (uint32_t)(r * FP + d8) * 2;
            cp16(kb + off, &K[(size_t)(k0 + r) * KVDIM + kvh * HD + d8]);
            cp16(vb + off, &V[(size_t)(k0 + r) * KVDIM + kvh * HD + d8]);
        }
        CP_COMMIT();
    };

#pragma unroll
    for (int i = 0; i < 4; i++) {
        int lin = tid + 256 * i;
        int r  = lin >> 3;
        int d8 = (lin & 7) << 3;
        *(uint4*)&Qs[r * FP + d8] =
            *(const uint4*)&Q[(size_t)(q0 + r) * DIM + h * HD + d8];
    }
    load_kv(0, 0);
    __syncthreads();

    uint32_t qf[4][4];
#pragma unroll
    for (int kk = 0; kk < 4; kk++) {
        qf[kk][0] = *(uint32_t*)&Qs[(qb + g)     * FP + kk * 16 + 2 * c];
        qf[kk][1] = *(uint32_t*)&Qs[(qb + g + 8) * FP + kk * 16 + 2 * c];
        qf[kk][2] = *(uint32_t*)&Qs[(qb + g)     * FP + kk * 16 + 2 * c + 8];
        qf[kk][3] = *(uint32_t*)&Qs[(qb + g + 8) * FP + kk * 16 + 2 * c + 8];
    }

    float m0 = -1e30f, m1 = -1e30f, l0 = 0.f, l1 = 0.f;
    float oacc[8][4] = {};

    for (int kt = 0; kt < NT; kt++) {
        const int buf = kt & 1;
        const int k0 = kt * 64;
        cp_wait<0>();
        __syncthreads();

        if (kt + 1 < NT) load_kv(kt + 1, buf ^ 1);

        if (k0 > q0 + qb + 15) continue;

        __half* Ks = fsm + FL_K0 + buf * KVBUF;
        const uint32_t vbyte = sbase + (uint32_t)(FL_V0 + buf * KVBUF) * 2;

        // S = Q K^T (log2 domain).
        float s[8][4] = {};
#pragma unroll
        for (int kk = 0; kk < 4; kk++) {
#pragma unroll
            for (int nt = 0; nt < 8; nt++) {
                uint32_t b[2];
                b[0] = *(uint32_t*)&Ks[(nt * 8 + g) * FP + kk * 16 + 2 * c];
                b[1] = *(uint32_t*)&Ks[(nt * 8 + g) * FP + kk * 16 + 2 * c + 8];
                mma_f16(s[nt], qf[kk], b);
            }
        }

        if (kt >= 2 * qt) {
            int r0 = q0 + qb + g, r1 = r0 + 8;
#pragma unroll
            for (int nt = 0; nt < 8; nt++) {
                int col = k0 + nt * 8 + 2 * c;
                if (col     > r0) s[nt][0] = -1e30f;
                if (col + 1 > r0) s[nt][1] = -1e30f;
                if (col     > r1) s[nt][2] = -1e30f;
                if (col + 1 > r1) s[nt][3] = -1e30f;
            }
        }

        // Online softmax (exp2 domain).
        float mx0 = -1e30f, mx1 = -1e30f;
#pragma unroll
        for (int nt = 0; nt < 8; nt++) {
            mx0 = fmaxf(mx0, fmaxf(s[nt][0], s[nt][1]));
            mx1 = fmaxf(mx1, fmaxf(s[nt][2], s[nt][3]));
        }
        mx0 = fmaxf(mx0, __shfl_xor_sync(0xffffffffu, mx0, 1));
        mx0 = fmaxf(mx0, __shfl_xor_sync(0xffffffffu, mx0, 2));
        mx1 = fmaxf(mx1, __shfl_xor_sync(0xffffffffu, mx1, 1));
        mx1 = fmaxf(mx1, __shfl_xor_sync(0xffffffffu, mx1, 2));

        float mn0 = fmaxf(m0, mx0), mn1 = fmaxf(m1, mx1);
        float al0 = exp2f(m0 - mn0), al1 = exp2f(m1 - mn1);
        float sum0 = 0.f, sum1 = 0.f;
#pragma unroll
        for (int nt = 0; nt < 8; nt++) {
            s[nt][0] = exp2f(s[nt][0] - mn0);
            s[nt][1] = exp2f(s[nt][1] - mn0);
            s[nt][2] = exp2f(s[nt][2] - mn1);
            s[nt][3] = exp2f(s[nt][3] - mn1);
            sum0 += s[nt][0] + s[nt][1];
            sum1 += s[nt][2] + s[nt][3];
        }
        sum0 += __shfl_xor_sync(0xffffffffu, sum0, 1);
        sum0 += __shfl_xor_sync(0xffffffffu, sum0, 2);
        sum1 += __shfl_xor_sync(0xffffffffu, sum1, 1);
        sum1 += __shfl_xor_sync(0xffffffffu, sum1, 2);
        l0 = l0 * al0 + sum0;  m0 = mn0;
        l1 = l1 * al1 + sum1;  m1 = mn1;
#pragma unroll
        for (int nt = 0; nt < 8; nt++) {
            oacc[nt][0] *= al0; oacc[nt][1] *= al0;
            oacc[nt][2] *= al1; oacc[nt][3] *= al1;
        }

        // O += P V; P A-fragments direct from S C-fragments.
#pragma unroll
        for (int kk = 0; kk < 4; kk++) {
            uint32_t a[4];
            a[0] = pack_h2(s[2 * kk][0],     s[2 * kk][1]);
            a[1] = pack_h2(s[2 * kk][2],     s[2 * kk][3]);
            a[2] = pack_h2(s[2 * kk + 1][0], s[2 * kk + 1][1]);
            a[3] = pack_h2(s[2 * kk + 1][2], s[2 * kk + 1][3]);
#pragma unroll
            for (int ntp = 0; ntp < 4; ntp++) {
                uint32_t addr = vbyte +
                    (uint32_t)(kk * 16 + lm_row) * (FP * 2) +
                    (uint32_t)(16 * ntp + 8 * lm_cs) * 2;
                uint32_t b0, b1, b2, b3;
                ldsm_x4_trans(b0, b1, b2, b3, addr);
                uint32_t blo[2] = {b0, b1}, bhi[2] = {b2, b3};
                mma_f16(oacc[2 * ntp],     a, blo);
                mma_f16(oacc[2 * ntp + 1], a, bhi);
            }
        }
    }

    float inv0 = 1.f / l0, inv1 = 1.f / l1;
    int r0 = q0 + qb + g;
#pragma unroll
    for (int nt = 0; nt < 8; nt++) {
        int col = h * HD + nt * 8 + 2 * c;
        *(uint32_t*)&O[(size_t)r0 * DIM + col] =
            pack_h2(oacc[nt][0] * inv0, oacc[nt][1] * inv0);
        *(uint32_t*)&O[(size_t)(r0 + 8) * DIM + col] =
            pack_h2(oacc[nt][2] * inv1, oacc[nt][3] * inv1);
    }
}

// ---------------------------------------------------------------------------
// Launch
// ---------------------------------------------------------------------------
extern "C" void kernel_launch(void* const* d_in, const int* in_sizes, int n_in,
                              void* d_out, int out_size) {
    const float* x  = (const float*)d_in[0];
    const float* fc = (const float*)d_in[1];
    const float* fs = (const float*)d_in[2];
    const float* wq = (const float*)d_in[3];
    const float* wk = (const float*)d_in[4];
    const float* wv = (const float*)d_in[5];
    const float* wo = (const float*)d_in[6];
    float* out = (float*)d_out;

    static __half *pq = nullptr, *pk, *pv, *pa, *px, *pwq, *pwk, *pwv, *pwo;
    if (!pq) {
        cudaGetSymbolAddress((void**)&pq,  g_qh);
        cudaGetSymbolAddress((void**)&pk,  g_kh);
        cudaGetSymbolAddress((void**)&pv,  g_vh);
        cudaGetSymbolAddress((void**)&pa,  g_ah);
        cudaGetSymbolAddress((void**)&px,  g_xh);
        cudaGetSymbolAddress((void**)&pwq, g_wqh);
        cudaGetSymbolAddress((void**)&pwk, g_wkh);
        cudaGetSymbolAddress((void**)&pwv, g_wvh);
        cudaGetSymbolAddress((void**)&pwo, g_woh);
        cudaFuncSetAttribute(flash_f16,
                             cudaFuncAttributeMaxDynamicSharedMemorySize,
                             FLASH_SMEM);
    }

    auto cvt = [&](const float* src, __half* dst, int n) {
        cvt_h<<<(n / 4 + 255) / 256, 256>>>((const float4*)src, (uint2*)dst,
                                            n / 4);
    };
    cvt(x,  px,  SEQ * DIM);
    cvt(wq, pwq, DIM * DIM);
    cvt(wk, pwk, KVDIM * DIM);
    cvt(wv, pwv, KVDIM * DIM);
    cvt(wo, pwo, DIM * DIM);

    dim3 blk(256);
    // Q proj: rope + (log2e / sqrt(64)) scale fused, half out.
    gemm_h<true, true><<<dim3(DIM / 64, SEQ / 128), blk>>>(
        px, pwq, pq, SEQ, DIM, DIM, fc, fs, 0.125f * LOG2E);
    // K proj: rope fused, half out.
    gemm_h<true, true><<<dim3(KVDIM / 64, SEQ / 128), blk>>>(
        px, pwk, pk, SEQ, KVDIM, DIM, fc, fs, 1.0f);
    // V proj: half out.
    gemm_h<false, true><<<dim3(KVDIM / 64, SEQ / 128), blk>>>(
        px, pwv, pv, SEQ, KVDIM, DIM, nullptr, nullptr, 1.0f);

    // Flash attention.
    flash_f16<<<dim3(SEQ / 128, NHEADS), blk, FLASH_SMEM>>>(pq, pk, pv, pa);

    // O proj: half operands, float out.
    gemm_h<false, false><<<dim3(DIM / 64, SEQ / 128), blk>>>(
        pa, pwo, out, SEQ, DIM, DIM, nullptr, nullptr, 1.0f);
}

// round 13
// speedup vs baseline: 1.2625x; 1.0264x over previous
#include <cuda_runtime.h>
#include <cuda_fp16.h>
#include <stdint.h>
#include <math.h>

#define SEQ     4096
#define DIM     1024
#define NHEADS  16
#define NKV     4
#define HD      64
#define KVDIM   256
#define LOG2E   1.44269504088896f

// ---------------------------------------------------------------------------
// Scratch (device globals; cudaMalloc forbidden) — fp16
// ---------------------------------------------------------------------------
__device__ __half g_qh[SEQ * DIM];
__device__ __half g_kh[SEQ * KVDIM];
__device__ __half g_vh[SEQ * KVDIM];
__device__ __half g_ah[SEQ * DIM];
__device__ __half g_xh[SEQ * DIM];
__device__ __half g_wqh[DIM * DIM];
__device__ __half g_wkh[KVDIM * DIM];
__device__ __half g_wvh[KVDIM * DIM];
__device__ __half g_woh[DIM * DIM];

// ---------------------------------------------------------------------------
// Helpers
// ---------------------------------------------------------------------------
__device__ __forceinline__ uint32_t pack_h2(float a, float b) {
    __half2 h = __floats2half2_rn(a, b);
    return *(uint32_t*)&h;
}
__device__ __forceinline__ uint32_t smem_u32(const void* p) {
    uint32_t a;
    asm("{ .reg .u64 t; cvta.to.shared.u64 t, %1; cvt.u32.u64 %0, t; }"
        : "=r"(a) : "l"(p));
    return a;
}
__device__ __forceinline__ void mma_f16(float c[4], const uint32_t a[4],
                                        const uint32_t b[2]) {
    asm volatile(
        "mma.sync.aligned.m16n8k16.row.col.f32.f16.f16.f32 "
        "{%0,%1,%2,%3},{%4,%5,%6,%7},{%8,%9},{%0,%1,%2,%3};"
        : "+f"(c[0]), "+f"(c[1]), "+f"(c[2]), "+f"(c[3])
        : "r"(a[0]), "r"(a[1]), "r"(a[2]), "r"(a[3]), "r"(b[0]), "r"(b[1]));
}
__device__ __forceinline__ void ldsm_x4(uint32_t& r0, uint32_t& r1,
                                        uint32_t& r2, uint32_t& r3,
                                        uint32_t addr) {
    asm volatile(
        "ldmatrix.sync.aligned.m8n8.x4.shared.b16 {%0,%1,%2,%3}, [%4];"
        : "=r"(r0), "=r"(r1), "=r"(r2), "=r"(r3) : "r"(addr));
}
__device__ __forceinline__ void ldsm_x4_trans(uint32_t& r0, uint32_t& r1,
                                              uint32_t& r2, uint32_t& r3,
                                              uint32_t addr) {
    asm volatile(
        "ldmatrix.sync.aligned.m8n8.x4.trans.shared.b16 {%0,%1,%2,%3}, [%4];"
        : "=r"(r0), "=r"(r1), "=r"(r2), "=r"(r3) : "r"(addr));
}
__device__ __forceinline__ void cp16(uint32_t dst, const void* src) {
    asm volatile("cp.async.cg.shared.global [%0], [%1], 16;"
                 :: "r"(dst), "l"(src));
}
#define CP_COMMIT() asm volatile("cp.async.commit_group;" ::: "memory")
template <int N>
__device__ __forceinline__ void cp_wait() {
    asm volatile("cp.async.wait_group %0;" :: "n"(N) : "memory");
}

// ---------------------------------------------------------------------------
// Fused fp32 -> fp16 conversion prepass (one launch for x + 4 weights)
// ---------------------------------------------------------------------------
#define N4_X   (SEQ * DIM / 4)
#define N4_WQ  (DIM * DIM / 4)
#define N4_WKV (KVDIM * DIM / 4)
#define N4_TOT (N4_X + N4_WQ + 2 * N4_WKV + N4_WQ)

__global__ void cvt_all(const float4* __restrict__ x,  uint2* __restrict__ xo,
                        const float4* __restrict__ wq, uint2* __restrict__ wqo,
                        const float4* __restrict__ wk, uint2* __restrict__ wko,
                        const float4* __restrict__ wv, uint2* __restrict__ wvo,
                        const float4* __restrict__ wo, uint2* __restrict__ woo) {
    int i = blockIdx.x * blockDim.x + threadIdx.x;
    if (i >= N4_TOT) return;
    const float4* src; uint2* dst; int j = i;
    if (j < N4_X)              { src = x;  dst = xo;  }
    else if ((j -= N4_X)  < N4_WQ)  { src = wq; dst = wqo; }
    else if ((j -= N4_WQ) < N4_WKV) { src = wk; dst = wko; }
    else if ((j -= N4_WKV) < N4_WKV){ src = wv; dst = wvo; }
    else { j -= N4_WKV;          src = wo; dst = woo; }
    float4 v = src[j];
    dst[j] = make_uint2(pack_h2(v.x, v.y), pack_h2(v.z, v.w));
}

// ---------------------------------------------------------------------------
// f16 GEMM: C[M,N] = alpha * A[M,K] @ B[N,K]^T, optional fused RoPE epilogue.
// A, B fp16 row-major. C half or float. cp.async double-buffered mainloop.
// BM=128, BN=64, BK=32, 256 threads (8 warps 4m x 2n), warp tile 32x32.
// ---------------------------------------------------------------------------
#define GAP 40

template <bool ROPE, bool CHALF>
__global__ __launch_bounds__(256) void gemm_h(const __half* __restrict__ A,
                                              const __half* __restrict__ B,
                                              void* __restrict__ Cp,
                                              int M, int N, int K,
                                              const float* __restrict__ cosb,
                                              const float* __restrict__ sinb,
                                              float alpha) {
    __shared__ __align__(16) __half As[2][128 * GAP];
    __shared__ __align__(16) __half Bs[2][64 * GAP];

    const int tid = threadIdx.x;
    const int wid = tid >> 5;
    const int lane = tid & 31;
    const int g = lane >> 2;
    const int c = lane & 3;
    const int wm = wid >> 1;
    const int wn = wid & 1;
    const int row0 = blockIdx.y * 128;
    const int col0 = blockIdx.x * 64;

    const uint32_t abase = smem_u32(&As[0][0]);
    const uint32_t bbase = smem_u32(&Bs[0][0]);

    auto load = [&](int i, int st) {
        int k0 = i * 32;
        uint32_t ab = abase + (uint32_t)st * (128 * GAP * 2);
        uint32_t bb = bbase + (uint32_t)st * (64 * GAP * 2);
#pragma unroll
        for (int j = 0; j < 2; j++) {
            int lin = tid + 256 * j;
            int r  = lin >> 2;
            int k8 = (lin & 3) << 3;
            cp16(ab + (uint32_t)(r * GAP + k8) * 2,
                 &A[(size_t)(row0 + r) * K + k0 + k8]);
        }
        {
            int r  = tid >> 2;
            int k8 = (tid & 3) << 3;
            cp16(bb + (uint32_t)(r * GAP + k8) * 2,
                 &B[(size_t)(col0 + r) * K + k0 + k8]);
        }
        CP_COMMIT();
    };

    float acc[2][4][4] = {};
    const int NI = K / 32;
    load(0, 0);

    for (int i = 0; i < NI; i++) {
        const int st = i & 1;
        if (i + 1 < NI) { load(i + 1, st ^ 1); cp_wait<1>(); }
        else           { cp_wait<0>(); }
        __syncthreads();

        const __half* Asb = As[st];
        const __half* Bsb = Bs[st];
#pragma unroll
        for (int kk = 0; kk < 2; kk++) {
            uint32_t a[2][4];
#pragma unroll
            for (int mt = 0; mt < 2; mt++) {
                int mb = wm * 32 + mt * 16;
                a[mt][0] = *(uint32_t*)&Asb[(mb + g)     * GAP + kk * 16 + 2 * c];
                a[mt][1] = *(uint32_t*)&Asb[(mb + g + 8) * GAP + kk * 16 + 2 * c];
                a[mt][2] = *(uint32_t*)&Asb[(mb + g)     * GAP + kk * 16 + 2 * c + 8];
                a[mt][3] = *(uint32_t*)&Asb[(mb + g + 8) * GAP + kk * 16 + 2 * c + 8];
            }
#pragma unroll
            for (int nt = 0; nt < 4; nt++) {
                int nb = wn * 32 + nt * 8;
                uint32_t b[2];
                b[0] = *(uint32_t*)&Bsb[(nb + g) * GAP + kk * 16 + 2 * c];
                b[1] = *(uint32_t*)&Bsb[(nb + g) * GAP + kk * 16 + 2 * c + 8];
#pragma unroll
                for (int mt = 0; mt < 2; mt++)
                    mma_f16(acc[mt][nt], a[mt], b);
            }
        }
        __syncthreads();
    }

    // Epilogue: optional scale + RoPE rotation, then store.
#pragma unroll
    for (int mt = 0; mt < 2; mt++) {
#pragma unroll
        for (int nt = 0; nt < 4; nt++) {
            int r = row0 + wm * 32 + mt * 16 + g;
            int col = col0 + wn * 32 + nt * 8 + 2 * c;
            float v0 = acc[mt][nt][0] * alpha;
            float v1 = acc[mt][nt][1] * alpha;
            float v2 = acc[mt][nt][2] * alpha;
            float v3 = acc[mt][nt][3] * alpha;
            if (ROPE) {
                int i = (col & 63) >> 1;
                float c0 = cosb[r * 32 + i],        s0 = sinb[r * 32 + i];
                float c1 = cosb[(r + 8) * 32 + i],  s1 = sinb[(r + 8) * 32 + i];
                float t0 = v0 * c0 - v1 * s0;
                float t1 = v0 * s0 + v1 * c0;
                float t2 = v2 * c1 - v3 * s1;
                float t3 = v2 * s1 + v3 * c1;
                v0 = t0; v1 = t1; v2 = t2; v3 = t3;
            }
            if (CHALF) {
                __half* C = (__half*)Cp;
                *(uint32_t*)&C[(size_t)r * N + col]       = pack_h2(v0, v1);
                *(uint32_t*)&C[(size_t)(r + 8) * N + col] = pack_h2(v2, v3);
            } else {
                float* C = (float*)Cp;
                *(float2*)&C[(size_t)r * N + col]       = make_float2(v0, v1);
                *(float2*)&C[(size_t)(r + 8) * N + col] = make_float2(v2, v3);
            }
        }
    }
}

// ---------------------------------------------------------------------------
// Flash attention, f16 m16n8k16, causal, GQA. fp16 in/out.
// Q pre-scaled by log2(e)/8 -> bare exp2f softmax. 256 threads; q-tile 128,
// k-tile 64; Q frags in registers; P in registers; K frags via ldmatrix.x4
// (non-trans), V frags via ldmatrix.x4.trans; K/V double-buffered cp.async.
// ---------------------------------------------------------------------------
#define FP 72
#define FL_QS 0
#define FL_K0 (128 * FP)
#define FL_V0 (FL_K0 + 64 * FP)
#define KVBUF (128 * FP)
#define FLASH_SMEM ((128 * FP + 2 * KVBUF) * 2)

extern __shared__ __half fsm[];

__global__ __launch_bounds__(256) void flash_f16(const __half* __restrict__ Q,
                                                 const __half* __restrict__ K,
                                                 const __half* __restrict__ V,
                                                 __half* __restrict__ O) {
    __half* Qs = fsm + FL_QS;

    const int qt = gridDim.x - 1 - blockIdx.x;
    const int h  = blockIdx.y;
    const int kvh = h >> 2;
    const int tid = threadIdx.x;
    const int w = tid >> 5;
    const int lane = tid & 31;
    const int g = lane >> 2;
    const int c = lane & 3;
    const int q0 = qt * 128;
    const int qb = w * 16;

    const uint32_t sbase = smem_u32(fsm);
    // V ldmatrix (trans) lane pieces
    const int lm_row = lane & 15;
    const int lm_cs  = (lane >> 4) & 1;
    // K ldmatrix (non-trans) lane pieces: matrix m = lane>>3
    const int km = lane >> 3;
    const int krow = lane & 7;
    const int k_key8 = (km >> 1) << 3;   // 0 or 8: key sub-group
    const int k_dim8 = (km & 1) << 3;    // 0 or 8: dim half

    const int NT = 2 * qt + 2;

    auto load_kv = [&](int kt, int buf) {
        const int k0 = kt * 64;
        uint32_t kb = sbase + (uint32_t)(FL_K0 + buf * KVBUF) * 2;
        uint32_t vb = sbase + (uint32_t)(FL_V0 + buf * KVBUF) * 2;
#pragma unroll
        for (int i = 0; i < 2; i++) {
            int lin = tid + 256 * i;
            int r  = lin >> 3;
            int d8 = (lin & 7) << 3;
            uint32_t off = (uint32_t)(r * FP + d8) * 2;
            cp16(kb + off, &K[(size_t)(k0 + r) * KVDIM + kvh * HD + d8]);
            cp16(vb + off, &V[(size_t)(k0 + r) * KVDIM + kvh * HD + d8]);
        }
        CP_COMMIT();
    };

#pragma unroll
    for (int i = 0; i < 4; i++) {
        int lin = tid + 256 * i;
        int r  = lin >> 3;
        int d8 = (lin & 7) << 3;
        *(uint4*)&Qs[r * FP + d8] =
            *(const uint4*)&Q[(size_t)(q0 + r) * DIM + h * HD + d8];
    }
    load_kv(0, 0);
    __syncthreads();

    uint32_t qf[4][4];
#pragma unroll
    for (int kk = 0; kk < 4; kk++) {
        qf[kk][0] = *(uint32_t*)&Qs[(qb + g)     * FP + kk * 16 + 2 * c];
        qf[kk][1] = *(uint32_t*)&Qs[(qb + g + 8) * FP + kk * 16 + 2 * c];
        qf[kk][2] = *(uint32_t*)&Qs[(qb + g)     * FP + kk * 16 + 2 * c + 8];
        qf[kk][3] = *(uint32_t*)&Qs[(qb + g + 8) * FP + kk * 16 + 2 * c + 8];
    }

    float m0 = -1e30f, m1 = -1e30f, l0 = 0.f, l1 = 0.f;
    float oacc[8][4] = {};

    for (int kt = 0; kt < NT; kt++) {
        const int buf = kt & 1;
        const int k0 = kt * 64;
        cp_wait<0>();
        __syncthreads();

        if (kt + 1 < NT) load_kv(kt + 1, buf ^ 1);

        if (k0 > q0 + qb + 15) continue;

        const uint32_t kbyte = sbase + (uint32_t)(FL_K0 + buf * KVBUF) * 2;
        const uint32_t vbyte = sbase + (uint32_t)(FL_V0 + buf * KVBUF) * 2;

        // S = Q K^T (log2 domain). K B-frags via ldmatrix.x4: one load gives
        // fragments for two adjacent n-tiles (keys 16*ntp + {0..7, 8..15}).
        float s[8][4] = {};
#pragma unroll
        for (int kk = 0; kk < 4; kk++) {
#pragma unroll
            for (int ntp = 0; ntp < 4; ntp++) {
                uint32_t addr = kbyte +
                    (uint32_t)((ntp * 16 + k_key8 + krow) * FP +
                               kk * 16 + k_dim8) * 2;
                uint32_t b0, b1, b2, b3;
                ldsm_x4(b0, b1, b2, b3, addr);
                uint32_t blo[2] = {b0, b1}, bhi[2] = {b2, b3};
                mma_f16(s[2 * ntp],     qf[kk], blo);
                mma_f16(s[2 * ntp + 1], qf[kk], bhi);
            }
        }

        if (kt >= 2 * qt) {
            int r0 = q0 + qb + g, r1 = r0 + 8;
#pragma unroll
            for (int nt = 0; nt < 8; nt++) {
                int col = k0 + nt * 8 + 2 * c;
                if (col     > r0) s[nt][0] = -1e30f;
                if (col + 1 > r0) s[nt][1] = -1e30f;
                if (col     > r1) s[nt][2] = -1e30f;
                if (col + 1 > r1) s[nt][3] = -1e30f;
            }
        }

        // Online softmax (exp2 domain).
        float mx0 = -1e30f, mx1 = -1e30f;
#pragma unroll
        for (int nt = 0; nt < 8; nt++) {
            mx0 = fmaxf(mx0, fmaxf(s[nt][0], s[nt][1]));
            mx1 = fmaxf(mx1, fmaxf(s[nt][2], s[nt][3]));
        }
        mx0 = fmaxf(mx0, __shfl_xor_sync(0xffffffffu, mx0, 1));
        mx0 = fmaxf(mx0, __shfl_xor_sync(0xffffffffu, mx0, 2));
        mx1 = fmaxf(mx1, __shfl_xor_sync(0xffffffffu, mx1, 1));
        mx1 = fmaxf(mx1, __shfl_xor_sync(0xffffffffu, mx1, 2));

        float mn0 = fmaxf(m0, mx0), mn1 = fmaxf(m1, mx1);
        float al0 = exp2f(m0 - mn0), al1 = exp2f(m1 - mn1);
        float sum0 = 0.f, sum1 = 0.f;
#pragma unroll
        for (int nt = 0; nt < 8; nt++) {
            s[nt][0] = exp2f(s[nt][0] - mn0);
            s[nt][1] = exp2f(s[nt][1] - mn0);
            s[nt][2] = exp2f(s[nt][2] - mn1);
            s[nt][3] = exp2f(s[nt][3] - mn1);
            sum0 += s[nt][0] + s[nt][1];
            sum1 += s[nt][2] + s[nt][3];
        }
        sum0 += __shfl_xor_sync(0xffffffffu, sum0, 1);
        sum0 += __shfl_xor_sync(0xffffffffu, sum0, 2);
        sum1 += __shfl_xor_sync(0xffffffffu, sum1, 1);
        sum1 += __shfl_xor_sync(0xffffffffu, sum1, 2);
        l0 = l0 * al0 + sum0;  m0 = mn0;
        l1 = l1 * al1 + sum1;  m1 = mn1;
#pragma unroll
        for (int nt = 0; nt < 8; nt++) {
            oacc[nt][0] *= al0; oacc[nt][1] *= al0;
            oacc[nt][2] *= al1; oacc[nt][3] *= al1;
        }

        // O += P V; P A-fragments direct from S C-fragments.
#pragma unroll
        for (int kk = 0; kk < 4; kk++) {
            uint32_t a[4];
            a[0] = pack_h2(s[2 * kk][0],     s[2 * kk][1]);
            a[1] = pack_h2(s[2 * kk][2],     s[2 * kk][3]);
            a[2] = pack_h2(s[2 * kk + 1][0], s[2 * kk + 1][1]);
            a[3] = pack_h2(s[2 * kk + 1][2], s[2 * kk + 1][3]);
#pragma unroll
            for (int ntp = 0; ntp < 4; ntp++) {
                uint32_t addr = vbyte +
                    (uint32_t)(kk * 16 + lm_row) * (FP * 2) +
                    (uint32_t)(16 * ntp + 8 * lm_cs) * 2;
                uint32_t b0, b1, b2, b3;
                ldsm_x4_trans(b0, b1, b2, b3, addr);
                uint32_t blo[2] = {b0, b1}, bhi[2] = {b2, b3};
                mma_f16(oacc[2 * ntp],     a, blo);
                mma_f16(oacc[2 * ntp + 1], a, bhi);
            }
        }
    }

    float inv0 = 1.f / l0, inv1 = 1.f / l1;
    int r0 = q0 + qb + g;
#pragma unroll
    for (int nt = 0; nt < 8; nt++) {
        int col = h * HD + nt * 8 + 2 * c;
        *(uint32_t*)&O[(size_t)r0 * DIM + col] =
            pack_h2(oacc[nt][0] * inv0, oacc[nt][1] * inv0);
        *(uint32_t*)&O[(size_t)(r0 + 8) * DIM + col] =
            pack_h2(oacc[nt][2] * inv1, oacc[nt][3] * inv1);
    }
}

// ---------------------------------------------------------------------------
// Launch
// ---------------------------------------------------------------------------
extern "C" void kernel_launch(void* const* d_in, const int* in_sizes, int n_in,
                              void* d_out, int out_size) {
    const float* x  = (const float*)d_in[0];
    const float* fc = (const float*)d_in[1];
    const float* fs = (const float*)d_in[2];
    const float* wq = (const float*)d_in[3];
    const float* wk = (const float*)d_in[4];
    const float* wv = (const float*)d_in[5];
    const float* wo = (const float*)d_in[6];
    float* out = (float*)d_out;

    static __half *pq = nullptr, *pk, *pv, *pa, *px, *pwq, *pwk, *pwv, *pwo;
    if (!pq) {
        cudaGetSymbolAddress((void**)&pq,  g_qh);
        cudaGetSymbolAddress((void**)&pk,  g_kh);
        cudaGetSymbolAddress((void**)&pv,  g_vh);
        cudaGetSymbolAddress((void**)&pa,  g_ah);
        cudaGetSymbolAddress((void**)&px,  g_xh);
        cudaGetSymbolAddress((void**)&pwq, g_wqh);
        cudaGetSymbolAddress((void**)&pwk, g_wkh);
        cudaGetSymbolAddress((void**)&pwv, g_wvh);
        cudaGetSymbolAddress((void**)&pwo, g_woh);
        cudaFuncSetAttribute(flash_f16,
                             cudaFuncAttributeMaxDynamicSharedMemorySize,
                             FLASH_SMEM);
    }

    // Single fused fp32->fp16 prepass.
    cvt_all<<<(N4_TOT + 255) / 256, 256>>>(
        (const float4*)x,  (uint2*)px,
        (const float4*)wq, (uint2*)pwq,
        (const float4*)wk, (uint2*)pwk,
        (const float4*)wv, (uint2*)pwv,
        (const float4*)wo, (uint2*)pwo);

    dim3 blk(256);
    // Q proj: rope + (log2e / sqrt(64)) scale fused, half out.
    gemm_h<true, true><<<dim3(DIM / 64, SEQ / 128), blk>>>(
        px, pwq, pq, SEQ, DIM, DIM, fc, fs, 0.125f * LOG2E);
    // K proj: rope fused, half out.
    gemm_h<true, true><<<dim3(KVDIM / 64, SEQ / 128), blk>>>(
        px, pwk, pk, SEQ, KVDIM, DIM, fc, fs, 1.0f);
    // V proj: half out.
    gemm_h<false, true><<<dim3(KVDIM / 64, SEQ / 128), blk>>>(
        px, pwv, pv, SEQ, KVDIM, DIM, nullptr, nullptr, 1.0f);

    // Flash attention.
    flash_f16<<<dim3(SEQ / 128, NHEADS), blk, FLASH_SMEM>>>(pq, pk, pv, pa);

    // O proj: half operands, float out.
    gemm_h<false, false><<<dim3(DIM / 64, SEQ / 128), blk>>>(
        pa, pwo, out, SEQ, DIM, DIM, nullptr, nullptr, 1.0f);
}

// round 14
// speedup vs baseline: 1.3276x; 1.0516x over previous
#include <cuda_runtime.h>
#include <cuda_fp16.h>
#include <stdint.h>
#include <math.h>

#define SEQ     4096
#define DIM     1024
#define NHEADS  16
#define NKV     4
#define HD      64
#define KVDIM   256
#define LOG2E   1.44269504088896f

// ---------------------------------------------------------------------------
// Scratch (device globals; cudaMalloc forbidden) — fp16
// ---------------------------------------------------------------------------
__device__ __half g_qh[SEQ * DIM];
__device__ __half g_kh[SEQ * KVDIM];
__device__ __half g_vh[SEQ * KVDIM];
__device__ __half g_ah[SEQ * DIM];
__device__ __half g_xh[SEQ * DIM];
__device__ __half g_wqh[DIM * DIM];
__device__ __half g_wkh[KVDIM * DIM];
__device__ __half g_wvh[KVDIM * DIM];
__device__ __half g_woh[DIM * DIM];

// ---------------------------------------------------------------------------
// Helpers
// ---------------------------------------------------------------------------
__device__ __forceinline__ uint32_t pack_h2(float a, float b) {
    __half2 h = __floats2half2_rn(a, b);
    return *(uint32_t*)&h;
}
__device__ __forceinline__ uint32_t smem_u32(const void* p) {
    uint32_t a;
    asm("{ .reg .u64 t; cvta.to.shared.u64 t, %1; cvt.u32.u64 %0, t; }"
        : "=r"(a) : "l"(p));
    return a;
}
__device__ __forceinline__ void mma_f16(float c[4], const uint32_t a[4],
                                        const uint32_t b[2]) {
    asm volatile(
        "mma.sync.aligned.m16n8k16.row.col.f32.f16.f16.f32 "
        "{%0,%1,%2,%3},{%4,%5,%6,%7},{%8,%9},{%0,%1,%2,%3};"
        : "+f"(c[0]), "+f"(c[1]), "+f"(c[2]), "+f"(c[3])
        : "r"(a[0]), "r"(a[1]), "r"(a[2]), "r"(a[3]), "r"(b[0]), "r"(b[1]));
}
__device__ __forceinline__ void ldsm_x4(uint32_t& r0, uint32_t& r1,
                                        uint32_t& r2, uint32_t& r3,
                                        uint32_t addr) {
    asm volatile(
        "ldmatrix.sync.aligned.m8n8.x4.shared.b16 {%0,%1,%2,%3}, [%4];"
        : "=r"(r0), "=r"(r1), "=r"(r2), "=r"(r3) : "r"(addr));
}
__device__ __forceinline__ void ldsm_x4_trans(uint32_t& r0, uint32_t& r1,
                                              uint32_t& r2, uint32_t& r3,
                                              uint32_t addr) {
    asm volatile(
        "ldmatrix.sync.aligned.m8n8.x4.trans.shared.b16 {%0,%1,%2,%3}, [%4];"
        : "=r"(r0), "=r"(r1), "=r"(r2), "=r"(r3) : "r"(addr));
}
__device__ __forceinline__ void cp16(uint32_t dst, const void* src) {
    asm volatile("cp.async.cg.shared.global [%0], [%1], 16;"
                 :: "r"(dst), "l"(src));
}
#define CP_COMMIT() asm volatile("cp.async.commit_group;" ::: "memory")
template <int N>
__device__ __forceinline__ void cp_wait() {
    asm volatile("cp.async.wait_group %0;" :: "n"(N) : "memory");
}

// ---------------------------------------------------------------------------
// Fused fp32 -> fp16 conversion prepass
// ---------------------------------------------------------------------------
#define N4_X   (SEQ * DIM / 4)
#define N4_WQ  (DIM * DIM / 4)
#define N4_WKV (KVDIM * DIM / 4)
#define N4_TOT (N4_X + N4_WQ + 2 * N4_WKV + N4_WQ)

__global__ void cvt_all(const float4* __restrict__ x,  uint2* __restrict__ xo,
                        const float4* __restrict__ wq, uint2* __restrict__ wqo,
                        const float4* __restrict__ wk, uint2* __restrict__ wko,
                        const float4* __restrict__ wv, uint2* __restrict__ wvo,
                        const float4* __restrict__ wo, uint2* __restrict__ woo) {
    int i = blockIdx.x * blockDim.x + threadIdx.x;
    if (i >= N4_TOT) return;
    const float4* src; uint2* dst; int j = i;
    if (j < N4_X)              { src = x;  dst = xo;  }
    else if ((j -= N4_X)  < N4_WQ)  { src = wq; dst = wqo; }
    else if ((j -= N4_WQ) < N4_WKV) { src = wk; dst = wko; }
    else if ((j -= N4_WKV) < N4_WKV){ src = wv; dst = wvo; }
    else { j -= N4_WKV;          src = wo; dst = woo; }
    float4 v = src[j];
    dst[j] = make_uint2(pack_h2(v.x, v.y), pack_h2(v.z, v.w));
}

// ---------------------------------------------------------------------------
// Fused QKV projection: one kernel over the concatenated 1536-col output.
// Grid x: 24 tiles of 64 cols -> [Q:0..1023 | K:1024..1279 | V:1280..1535].
// BM=128, BK=32, 256 threads, cp.async double-buffered. RoPE fused for Q,K;
// Q also scaled by log2e/8. 768 blocks total (vs 128+128+512 split before).
// ---------------------------------------------------------------------------
#define GAP 40

__global__ __launch_bounds__(256) void gemm_qkv(const __half* __restrict__ X,
                                                const __half* __restrict__ Wq,
                                                const __half* __restrict__ Wk,
                                                const __half* __restrict__ Wv,
                                                __half* __restrict__ Oq,
                                                __half* __restrict__ Ok,
                                                __half* __restrict__ Ov,
                                                const float* __restrict__ cosb,
                                                const float* __restrict__ sinb) {
    __shared__ __align__(16) __half As[2][128 * GAP];
    __shared__ __align__(16) __half Bs[2][64 * GAP];

    const int tid = threadIdx.x;
    const int wid = tid >> 5;
    const int lane = tid & 31;
    const int g = lane >> 2;
    const int c = lane & 3;
    const int wm = wid >> 1;
    const int wn = wid & 1;
    const int row0 = blockIdx.y * 128;
    const int col0 = blockIdx.x * 64;
    const int K = DIM;

    // Block-uniform segment select.
    const __half* Bp; __half* Cp; int bc, Nn; bool rope; float alpha;
    if (col0 < DIM)               { Bp = Wq; Cp = Oq; bc = col0;               Nn = DIM;   rope = true;  alpha = 0.125f * LOG2E; }
    else if (col0 < DIM + KVDIM)  { Bp = Wk; Cp = Ok; bc = col0 - DIM;         Nn = KVDIM; rope = true;  alpha = 1.0f; }
    else                          { Bp = Wv; Cp = Ov; bc = col0 - DIM - KVDIM; Nn = KVDIM; rope = false; alpha = 1.0f; }

    const uint32_t abase = smem_u32(&As[0][0]);
    const uint32_t bbase = smem_u32(&Bs[0][0]);

    auto load = [&](int i, int st) {
        int k0 = i * 32;
        uint32_t ab = abase + (uint32_t)st * (128 * GAP * 2);
        uint32_t bb = bbase + (uint32_t)st * (64 * GAP * 2);
#pragma unroll
        for (int j = 0; j < 2; j++) {
            int lin = tid + 256 * j;
            int r  = lin >> 2;
            int k8 = (lin & 3) << 3;
            cp16(ab + (uint32_t)(r * GAP + k8) * 2,
                 &X[(size_t)(row0 + r) * K + k0 + k8]);
        }
        {
            int r  = tid >> 2;
            int k8 = (tid & 3) << 3;
            cp16(bb + (uint32_t)(r * GAP + k8) * 2,
                 &Bp[(size_t)(bc + r) * K + k0 + k8]);
        }
        CP_COMMIT();
    };

    float acc[2][4][4] = {};
    const int NI = K / 32;
    load(0, 0);

    for (int i = 0; i < NI; i++) {
        const int st = i & 1;
        if (i + 1 < NI) { load(i + 1, st ^ 1); cp_wait<1>(); }
        else           { cp_wait<0>(); }
        __syncthreads();

        const __half* Asb = As[st];
        const __half* Bsb = Bs[st];
#pragma unroll
        for (int kk = 0; kk < 2; kk++) {
            uint32_t a[2][4];
#pragma unroll
            for (int mt = 0; mt < 2; mt++) {
                int mb = wm * 32 + mt * 16;
                a[mt][0] = *(uint32_t*)&Asb[(mb + g)     * GAP + kk * 16 + 2 * c];
                a[mt][1] = *(uint32_t*)&Asb[(mb + g + 8) * GAP + kk * 16 + 2 * c];
                a[mt][2] = *(uint32_t*)&Asb[(mb + g)     * GAP + kk * 16 + 2 * c + 8];
                a[mt][3] = *(uint32_t*)&Asb[(mb + g + 8) * GAP + kk * 16 + 2 * c + 8];
            }
#pragma unroll
            for (int nt = 0; nt < 4; nt++) {
                int nb = wn * 32 + nt * 8;
                uint32_t b[2];
                b[0] = *(uint32_t*)&Bsb[(nb + g) * GAP + kk * 16 + 2 * c];
                b[1] = *(uint32_t*)&Bsb[(nb + g) * GAP + kk * 16 + 2 * c + 8];
#pragma unroll
                for (int mt = 0; mt < 2; mt++)
                    mma_f16(acc[mt][nt], a[mt], b);
            }
        }
        __syncthreads();
    }

    // Epilogue: scale + optional RoPE, fp16 store.
#pragma unroll
    for (int mt = 0; mt < 2; mt++) {
#pragma unroll
        for (int nt = 0; nt < 4; nt++) {
            int r = row0 + wm * 32 + mt * 16 + g;
            int cc = (bc) + wn * 32 + nt * 8 + 2 * c;
            float v0 = acc[mt][nt][0] * alpha;
            float v1 = acc[mt][nt][1] * alpha;
            float v2 = acc[mt][nt][2] * alpha;
            float v3 = acc[mt][nt][3] * alpha;
            if (rope) {
                int i = (cc & 63) >> 1;
                float c0 = cosb[r * 32 + i],        s0 = sinb[r * 32 + i];
                float c1 = cosb[(r + 8) * 32 + i],  s1 = sinb[(r + 8) * 32 + i];
                float t0 = v0 * c0 - v1 * s0;
                float t1 = v0 * s0 + v1 * c0;
                float t2 = v2 * c1 - v3 * s1;
                float t3 = v2 * s1 + v3 * c1;
                v0 = t0; v1 = t1; v2 = t2; v3 = t3;
            }
            *(uint32_t*)&Cp[(size_t)r * Nn + cc]       = pack_h2(v0, v1);
            *(uint32_t*)&Cp[(size_t)(r + 8) * Nn + cc] = pack_h2(v2, v3);
        }
    }
}

// ---------------------------------------------------------------------------
// O-projection: fp16 A,B -> fp32 C. Same tiling as before.
// ---------------------------------------------------------------------------
__global__ __launch_bounds__(256) void gemm_o(const __half* __restrict__ A,
                                              const __half* __restrict__ B,
                                              float* __restrict__ C,
                                              int M, int N, int K) {
    __shared__ __align__(16) __half As[2][128 * GAP];
    __shared__ __align__(16) __half Bs[2][64 * GAP];

    const int tid = threadIdx.x;
    const int wid = tid >> 5;
    const int lane = tid & 31;
    const int g = lane >> 2;
    const int c = lane & 3;
    const int wm = wid >> 1;
    const int wn = wid & 1;
    const int row0 = blockIdx.y * 128;
    const int col0 = blockIdx.x * 64;

    const uint32_t abase = smem_u32(&As[0][0]);
    const uint32_t bbase = smem_u32(&Bs[0][0]);

    auto load = [&](int i, int st) {
        int k0 = i * 32;
        uint32_t ab = abase + (uint32_t)st * (128 * GAP * 2);
        uint32_t bb = bbase + (uint32_t)st * (64 * GAP * 2);
#pragma unroll
        for (int j = 0; j < 2; j++) {
            int lin = tid + 256 * j;
            int r  = lin >> 2;
            int k8 = (lin & 3) << 3;
            cp16(ab + (uint32_t)(r * GAP + k8) * 2,
                 &A[(size_t)(row0 + r) * K + k0 + k8]);
        }
        {
            int r  = tid >> 2;
            int k8 = (tid & 3) << 3;
            cp16(bb + (uint32_t)(r * GAP + k8) * 2,
                 &B[(size_t)(col0 + r) * K + k0 + k8]);
        }
        CP_COMMIT();
    };

    float acc[2][4][4] = {};
    const int NI = K / 32;
    load(0, 0);

    for (int i = 0; i < NI; i++) {
        const int st = i & 1;
        if (i + 1 < NI) { load(i + 1, st ^ 1); cp_wait<1>(); }
        else           { cp_wait<0>(); }
        __syncthreads();

        const __half* Asb = As[st];
        const __half* Bsb = Bs[st];
#pragma unroll
        for (int kk = 0; kk < 2; kk++) {
            uint32_t a[2][4];
#pragma unroll
            for (int mt = 0; mt < 2; mt++) {
                int mb = wm * 32 + mt * 16;
                a[mt][0] = *(uint32_t*)&Asb[(mb + g)     * GAP + kk * 16 + 2 * c];
                a[mt][1] = *(uint32_t*)&Asb[(mb + g + 8) * GAP + kk * 16 + 2 * c];
                a[mt][2] = *(uint32_t*)&Asb[(mb + g)     * GAP + kk * 16 + 2 * c + 8];
                a[mt][3] = *(uint32_t*)&Asb[(mb + g + 8) * GAP + kk * 16 + 2 * c + 8];
            }
#pragma unroll
            for (int nt = 0; nt < 4; nt++) {
                int nb = wn * 32 + nt * 8;
                uint32_t b[2];
                b[0] = *(uint32_t*)&Bsb[(nb + g) * GAP + kk * 16 + 2 * c];
                b[1] = *(uint32_t*)&Bsb[(nb + g) * GAP + kk * 16 + 2 * c + 8];
#pragma unroll
                for (int mt = 0; mt < 2; mt++)
                    mma_f16(acc[mt][nt], a[mt], b);
            }
        }
        __syncthreads();
    }

#pragma unroll
    for (int mt = 0; mt < 2; mt++) {
#pragma unroll
        for (int nt = 0; nt < 4; nt++) {
            int r = row0 + wm * 32 + mt * 16 + g;
            int col = col0 + wn * 32 + nt * 8 + 2 * c;
            *(float2*)&C[(size_t)r * N + col] =
                make_float2(acc[mt][nt][0], acc[mt][nt][1]);
            *(float2*)&C[(size_t)(r + 8) * N + col] =
                make_float2(acc[mt][nt][2], acc[mt][nt][3]);
        }
    }
}

// ---------------------------------------------------------------------------
// Flash attention, f16 m16n8k16, causal, GQA. fp16 in/out.
// Q pre-scaled by log2e/8 -> bare exp2f softmax. 256 threads; q-tile 128.
// K/V loaded 128 keys per cp.async stage (half the barrier/wait count),
// compute runs two 64-key softmax passes per stage. Q frags in registers;
// P in registers; K frags ldmatrix.x4; V frags ldmatrix.x4.trans.
// Smem: Q 128x72 + 2 x (K 128x72 + V 128x72) = 92160 B.
// ---------------------------------------------------------------------------
#define FP 72
#define FL_QS 0
#define FL_K0 (128 * FP)
#define FL_V0 (FL_K0 + 128 * FP)
#define KVBUF (256 * FP)
#define FLASH_SMEM ((128 * FP + 2 * KVBUF) * 2)

extern __shared__ __half fsm[];

__global__ __launch_bounds__(256) void flash_f16(const __half* __restrict__ Q,
                                                 const __half* __restrict__ K,
                                                 const __half* __restrict__ V,
                                                 __half* __restrict__ O) {
    __half* Qs = fsm + FL_QS;

    const int qt = gridDim.x - 1 - blockIdx.x;
    const int h  = blockIdx.y;
    const int kvh = h >> 2;
    const int tid = threadIdx.x;
    const int w = tid >> 5;
    const int lane = tid & 31;
    const int g = lane >> 2;
    const int c = lane & 3;
    const int q0 = qt * 128;
    const int qb = w * 16;

    const uint32_t sbase = smem_u32(fsm);
    const int lm_row = lane & 15;
    const int lm_cs  = (lane >> 4) & 1;
    const int km = lane >> 3;
    const int krow = lane & 7;
    const int k_key8 = (km >> 1) << 3;
    const int k_dim8 = (km & 1) << 3;

    const int NT = qt + 1;              // 128-key stages

    auto load_kv = [&](int kt, int buf) {
        const int k0 = kt * 128;
        uint32_t kb = sbase + (uint32_t)(FL_K0 + buf * KVBUF) * 2;
        uint32_t vb = sbase + (uint32_t)(FL_V0 + buf * KVBUF) * 2;
#pragma unroll
        for (int i = 0; i < 4; i++) {
            int lin = tid + 256 * i;    // 0..1023
            int r  = lin >> 3;          // 0..127
            int d8 = (lin & 7) << 3;
            uint32_t off = (uint32_t)(r * FP + d8) * 2;
            cp16(kb + off, &K[(size_t)(k0 + r) * KVDIM + kvh * HD + d8]);
            cp16(vb + off, &V[(size_t)(k0 + r) * KVDIM + kvh * HD + d8]);
        }
        CP_COMMIT();
    };

#pragma unroll
    for (int i = 0; i < 4; i++) {
        int lin = tid + 256 * i;
        int r  = lin >> 3;
        int d8 = (lin & 7) << 3;
        *(uint4*)&Qs[r * FP + d8] =
            *(const uint4*)&Q[(size_t)(q0 + r) * DIM + h * HD + d8];
    }
    load_kv(0, 0);
    __syncthreads();

    uint32_t qf[4][4];
#pragma unroll
    for (int kk = 0; kk < 4; kk++) {
        qf[kk][0] = *(uint32_t*)&Qs[(qb + g)     * FP + kk * 16 + 2 * c];
        qf[kk][1] = *(uint32_t*)&Qs[(qb + g + 8) * FP + kk * 16 + 2 * c];
        qf[kk][2] = *(uint32_t*)&Qs[(qb + g)     * FP + kk * 16 + 2 * c + 8];
        qf[kk][3] = *(uint32_t*)&Qs[(qb + g + 8) * FP + kk * 16 + 2 * c + 8];
    }

    float m0 = -1e30f, m1 = -1e30f, l0 = 0.f, l1 = 0.f;
    float oacc[8][4] = {};

    for (int kt = 0; kt < NT; kt++) {
        const int buf = kt & 1;
        cp_wait<0>();
        __syncthreads();

        if (kt + 1 < NT) load_kv(kt + 1, buf ^ 1);

#pragma unroll
        for (int half = 0; half < 2; half++) {
            const int k0 = kt * 128 + half * 64;
            if (k0 > q0 + qb + 15) continue;   // warp-uniform skip

            const uint32_t kbyte = sbase +
                (uint32_t)(FL_K0 + buf * KVBUF + half * 64 * FP) * 2;
            const uint32_t vbyte = sbase +
                (uint32_t)(FL_V0 + buf * KVBUF + half * 64 * FP) * 2;

            // S = Q K^T (log2 domain); K frags via ldmatrix.x4.
            float s[8][4] = {};
#pragma unroll
            for (int kk = 0; kk < 4; kk++) {
#pragma unroll
                for (int ntp = 0; ntp < 4; ntp++) {
                    uint32_t addr = kbyte +
                        (uint32_t)((ntp * 16 + k_key8 + krow) * FP +
                                   kk * 16 + k_dim8) * 2;
                    uint32_t b0, b1, b2, b3;
                    ldsm_x4(b0, b1, b2, b3, addr);
                    uint32_t blo[2] = {b0, b1}, bhi[2] = {b2, b3};
                    mma_f16(s[2 * ntp],     qf[kk], blo);
                    mma_f16(s[2 * ntp + 1], qf[kk], bhi);
                }
            }

            // Causal mask (warp-uniform condition; mask is idempotent).
            if (k0 + 63 > q0 + qb) {
                int r0 = q0 + qb + g, r1 = r0 + 8;
#pragma unroll
                for (int nt = 0; nt < 8; nt++) {
                    int col = k0 + nt * 8 + 2 * c;
                    if (col     > r0) s[nt][0] = -1e30f;
                    if (col + 1 > r0) s[nt][1] = -1e30f;
                    if (col     > r1) s[nt][2] = -1e30f;
                    if (col + 1 > r1) s[nt][3] = -1e30f;
                }
            }

            // Online softmax (exp2 domain).
            float mx0 = -1e30f, mx1 = -1e30f;
#pragma unroll
            for (int nt = 0; nt < 8; nt++) {
                mx0 = fmaxf(mx0, fmaxf(s[nt][0], s[nt][1]));
                mx1 = fmaxf(mx1, fmaxf(s[nt][2], s[nt][3]));
            }
            mx0 = fmaxf(mx0, __shfl_xor_sync(0xffffffffu, mx0, 1));
            mx0 = fmaxf(mx0, __shfl_xor_sync(0xffffffffu, mx0, 2));
            mx1 = fmaxf(mx1, __shfl_xor_sync(0xffffffffu, mx1, 1));
            mx1 = fmaxf(mx1, __shfl_xor_sync(0xffffffffu, mx1, 2));

            float mn0 = fmaxf(m0, mx0), mn1 = fmaxf(m1, mx1);
            float al0 = exp2f(m0 - mn0), al1 = exp2f(m1 - mn1);
            float sum0 = 0.f, sum1 = 0.f;
#pragma unroll
            for (int nt = 0; nt < 8; nt++) {
                s[nt][0] = exp2f(s[nt][0] - mn0);
                s[nt][1] = exp2f(s[nt][1] - mn0);
                s[nt][2] = exp2f(s[nt][2] - mn1);
                s[nt][3] = exp2f(s[nt][3] - mn1);
                sum0 += s[nt][0] + s[nt][1];
                sum1 += s[nt][2] + s[nt][3];
            }
            sum0 += __shfl_xor_sync(0xffffffffu, sum0, 1);
            sum0 += __shfl_xor_sync(0xffffffffu, sum0, 2);
            sum1 += __shfl_xor_sync(0xffffffffu, sum1, 1);
            sum1 += __shfl_xor_sync(0xffffffffu, sum1, 2);
            l0 = l0 * al0 + sum0;  m0 = mn0;
            l1 = l1 * al1 + sum1;  m1 = mn1;
#pragma unroll
            for (int nt = 0; nt < 8; nt++) {
                oacc[nt][0] *= al0; oacc[nt][1] *= al0;
                oacc[nt][2] *= al1; oacc[nt][3] *= al1;
            }

            // O += P V; P A-fragments direct from S C-fragments.
#pragma unroll
            for (int kk = 0; kk < 4; kk++) {
                uint32_t a[4];
                a[0] = pack_h2(s[2 * kk][0],     s[2 * kk][1]);
                a[1] = pack_h2(s[2 * kk][2],     s[2 * kk][3]);
                a[2] = pack_h2(s[2 * kk + 1][0], s[2 * kk + 1][1]);
                a[3] = pack_h2(s[2 * kk + 1][2], s[2 * kk + 1][3]);
#pragma unroll
                for (int ntp = 0; ntp < 4; ntp++) {
                    uint32_t addr = vbyte +
                        (uint32_t)(kk * 16 + lm_row) * (FP * 2) +
                        (uint32_t)(16 * ntp + 8 * lm_cs) * 2;
                    uint32_t b0, b1, b2, b3;
                    ldsm_x4_trans(b0, b1, b2, b3, addr);
                    uint32_t blo[2] = {b0, b1}, bhi[2] = {b2, b3};
                    mma_f16(oacc[2 * ntp],     a, blo);
                    mma_f16(oacc[2 * ntp + 1], a, bhi);
                }
            }
        }
    }

    float inv0 = 1.f / l0, inv1 = 1.f / l1;
    int r0 = q0 + qb + g;
#pragma unroll
    for (int nt = 0; nt < 8; nt++) {
        int col = h * HD + nt * 8 + 2 * c;
        *(uint32_t*)&O[(size_t)r0 * DIM + col] =
            pack_h2(oacc[nt][0] * inv0, oacc[nt][1] * inv0);
        *(uint32_t*)&O[(size_t)(r0 + 8) * DIM + col] =
            pack_h2(oacc[nt][2] * inv1, oacc[nt][3] * inv1);
    }
}

// ---------------------------------------------------------------------------
// Launch
// ---------------------------------------------------------------------------
extern "C" void kernel_launch(void* const* d_in, const int* in_sizes, int n_in,
                              void* d_out, int out_size) {
    const float* x  = (const float*)d_in[0];
    const float* fc = (const float*)d_in[1];
    const float* fs = (const float*)d_in[2];
    const float* wq = (const float*)d_in[3];
    const float* wk = (const float*)d_in[4];
    const float* wv = (const float*)d_in[5];
    const float* wo = (const float*)d_in[6];
    float* out = (float*)d_out;

    static __half *pq = nullptr, *pk, *pv, *pa, *px, *pwq, *pwk, *pwv, *pwo;
    if (!pq) {
        cudaGetSymbolAddress((void**)&pq,  g_qh);
        cudaGetSymbolAddress((void**)&pk,  g_kh);
        cudaGetSymbolAddress((void**)&pv,  g_vh);
        cudaGetSymbolAddress((void**)&pa,  g_ah);
        cudaGetSymbolAddress((void**)&px,  g_xh);
        cudaGetSymbolAddress((void**)&pwq, g_wqh);
        cudaGetSymbolAddress((void**)&pwk, g_wkh);
        cudaGetSymbolAddress((void**)&pwv, g_wvh);
        cudaGetSymbolAddress((void**)&pwo, g_woh);
        cudaFuncSetAttribute(flash_f16,
                             cudaFuncAttributeMaxDynamicSharedMemorySize,
                             FLASH_SMEM);
    }

    // Single fused fp32->fp16 prepass.
    cvt_all<<<(N4_TOT + 255) / 256, 256>>>(
        (const float4*)x,  (uint2*)px,
        (const float4*)wq, (uint2*)pwq,
        (const float4*)wk, (uint2*)pwk,
        (const float4*)wv, (uint2*)pwv,
        (const float4*)wo, (uint2*)pwo);

    dim3 blk(256);
    // Fused QKV projection (768 blocks), rope + scaling in epilogue.
    gemm_qkv<<<dim3((DIM + 2 * KVDIM) / 64, SEQ / 128), blk>>>(
        px, pwq, pwk, pwv, pq, pk, pv, fc, fs);

    // Flash attention.
    flash_f16<<<dim3(SEQ / 128, NHEADS), blk, FLASH_SMEM>>>(pq, pk, pv, pa);

    // O projection.
    gemm_o<<<dim3(DIM / 64, SEQ / 128), blk>>>(pa, pwo, out, SEQ, DIM, DIM);
}

// round 15
// speedup vs baseline: 1.4508x; 1.0928x over previous
#include <cuda_runtime.h>
#include <cuda_fp16.h>
#include <stdint.h>
#include <math.h>

#define SEQ     4096
#define DIM     1024
#define NHEADS  16
#define NKV     4
#define HD      64
#define KVDIM   256
#define LOG2E   1.44269504088896f

// ---------------------------------------------------------------------------
// Scratch (device globals; cudaMalloc forbidden) — fp16
// ---------------------------------------------------------------------------
__device__ __half g_qh[SEQ * DIM];
__device__ __half g_kh[SEQ * KVDIM];
__device__ __half g_vh[SEQ * KVDIM];
__device__ __half g_ah[SEQ * DIM];
__device__ __half g_xh[SEQ * DIM];
__device__ __half g_wqh[DIM * DIM];
__device__ __half g_wkh[KVDIM * DIM];
__device__ __half g_wvh[KVDIM * DIM];
__device__ __half g_woh[DIM * DIM];

// ---------------------------------------------------------------------------
// Helpers
// ---------------------------------------------------------------------------
__device__ __forceinline__ uint32_t pack_h2(float a, float b) {
    __half2 h = __floats2half2_rn(a, b);
    return *(uint32_t*)&h;
}
__device__ __forceinline__ uint32_t smem_u32(const void* p) {
    uint32_t a;
    asm("{ .reg .u64 t; cvta.to.shared.u64 t, %1; cvt.u32.u64 %0, t; }"
        : "=r"(a) : "l"(p));
    return a;
}
__device__ __forceinline__ void mma_f16(float c[4], const uint32_t a[4],
                                        const uint32_t b[2]) {
    asm volatile(
        "mma.sync.aligned.m16n8k16.row.col.f32.f16.f16.f32 "
        "{%0,%1,%2,%3},{%4,%5,%6,%7},{%8,%9},{%0,%1,%2,%3};"
        : "+f"(c[0]), "+f"(c[1]), "+f"(c[2]), "+f"(c[3])
        : "r"(a[0]), "r"(a[1]), "r"(a[2]), "r"(a[3]), "r"(b[0]), "r"(b[1]));
}
__device__ __forceinline__ void ldsm_x4(uint32_t& r0, uint32_t& r1,
                                        uint32_t& r2, uint32_t& r3,
                                        uint32_t addr) {
    asm volatile(
        "ldmatrix.sync.aligned.m8n8.x4.shared.b16 {%0,%1,%2,%3}, [%4];"
        : "=r"(r0), "=r"(r1), "=r"(r2), "=r"(r3) : "r"(addr));
}
__device__ __forceinline__ void ldsm_x4_trans(uint32_t& r0, uint32_t& r1,
                                              uint32_t& r2, uint32_t& r3,
                                              uint32_t addr) {
    asm volatile(
        "ldmatrix.sync.aligned.m8n8.x4.trans.shared.b16 {%0,%1,%2,%3}, [%4];"
        : "=r"(r0), "=r"(r1), "=r"(r2), "=r"(r3) : "r"(addr));
}
__device__ __forceinline__ void cp16(uint32_t dst, const void* src) {
    asm volatile("cp.async.cg.shared.global [%0], [%1], 16;"
                 :: "r"(dst), "l"(src));
}
#define CP_COMMIT() asm volatile("cp.async.commit_group;" ::: "memory")
template <int N>
__device__ __forceinline__ void cp_wait() {
    asm volatile("cp.async.wait_group %0;" :: "n"(N) : "memory");
}

// ---------------------------------------------------------------------------
// Fused fp32 -> fp16 conversion prepass
// ---------------------------------------------------------------------------
#define N4_X   (SEQ * DIM / 4)
#define N4_WQ  (DIM * DIM / 4)
#define N4_WKV (KVDIM * DIM / 4)
#define N4_TOT (N4_X + N4_WQ + 2 * N4_WKV + N4_WQ)

__global__ void cvt_all(const float4* __restrict__ x,  uint2* __restrict__ xo,
                        const float4* __restrict__ wq, uint2* __restrict__ wqo,
                        const float4* __restrict__ wk, uint2* __restrict__ wko,
                        const float4* __restrict__ wv, uint2* __restrict__ wvo,
                        const float4* __restrict__ wo, uint2* __restrict__ woo) {
    int i = blockIdx.x * blockDim.x + threadIdx.x;
    if (i >= N4_TOT) return;
    const float4* src; uint2* dst; int j = i;
    if (j < N4_X)              { src = x;  dst = xo;  }
    else if ((j -= N4_X)  < N4_WQ)  { src = wq; dst = wqo; }
    else if ((j -= N4_WQ) < N4_WKV) { src = wk; dst = wko; }
    else if ((j -= N4_WKV) < N4_WKV){ src = wv; dst = wvo; }
    else { j -= N4_WKV;          src = wo; dst = woo; }
    float4 v = src[j];
    dst[j] = make_uint2(pack_h2(v.x, v.y), pack_h2(v.z, v.w));
}

// ---------------------------------------------------------------------------
// GEMM mainloop core (shared): BM=128, BN=64, BK=64, 256 thr, 2-stage
// cp.async, ldmatrix.x4 fragments. Dynamic smem 55296 B.
// A stage: 128 x 72 halves; B stage: 64 x 72 halves.
// ---------------------------------------------------------------------------
#define GP2   72
#define GA_ST (128 * GP2)
#define GB_ST (64 * GP2)
#define GEMM_SMEM ((2 * GA_ST + 2 * GB_ST) * 2)

extern __shared__ __half fsm[];

// Computes acc for one 128x64 C tile. Apb = A row base, Bpb = B row base.
template <typename EPI>
__device__ __forceinline__ void gemm_core(const __half* __restrict__ A,
                                          const __half* __restrict__ Bp,
                                          int row0, int bc, int K, EPI epi) {
    const int tid = threadIdx.x;
    const int wid = tid >> 5;
    const int lane = tid & 31;
    const int wm = wid >> 1;
    const int wn = wid & 1;

    const uint32_t abase = smem_u32(fsm);
    const uint32_t bbase = abase + 2 * GA_ST * 2;

    // ldmatrix lane pieces
    const int km = lane >> 3;
    const int krow = lane & 7;
    const int a_row = ((km & 1) << 3) + krow;   // row within 16
    const int a_col = (km >> 1) << 3;           // dim half
    const int b_key8 = (km >> 1) << 3;
    const int b_dim8 = (km & 1) << 3;

    auto load = [&](int i, int st) {
        int k0 = i * 64;
        uint32_t ab = abase + (uint32_t)st * (GA_ST * 2);
        uint32_t bb = bbase + (uint32_t)st * (GB_ST * 2);
#pragma unroll
        for (int j = 0; j < 4; j++) {
            int lin = tid + 256 * j;        // 0..1023
            int r  = lin >> 3;              // 0..127
            int d8 = (lin & 7) << 3;        // 0..56
            cp16(ab + (uint32_t)(r * GP2 + d8) * 2,
                 &A[(size_t)(row0 + r) * K + k0 + d8]);
        }
#pragma unroll
        for (int j = 0; j < 2; j++) {
            int lin = tid + 256 * j;        // 0..511
            int r  = lin >> 3;              // 0..63
            int d8 = (lin & 7) << 3;
            cp16(bb + (uint32_t)(r * GP2 + d8) * 2,
                 &Bp[(size_t)(bc + r) * K + k0 + d8]);
        }
        CP_COMMIT();
    };

    float acc[2][4][4] = {};
    const int NI = K / 64;
    load(0, 0);

    for (int i = 0; i < NI; i++) {
        const int st = i & 1;
        if (i + 1 < NI) { load(i + 1, st ^ 1); cp_wait<1>(); }
        else           { cp_wait<0>(); }
        __syncthreads();

        const uint32_t ab = abase + (uint32_t)st * (GA_ST * 2);
        const uint32_t bb = bbase + (uint32_t)st * (GB_ST * 2);
#pragma unroll
        for (int kk = 0; kk < 4; kk++) {
            uint32_t a[2][4];
#pragma unroll
            for (int mt = 0; mt < 2; mt++) {
                int mb = wm * 32 + mt * 16;
                uint32_t addr = ab +
                    (uint32_t)((mb + a_row) * GP2 + kk * 16 + a_col) * 2;
                ldsm_x4(a[mt][0], a[mt][1], a[mt][2], a[mt][3], addr);
            }
#pragma unroll
            for (int ntp = 0; ntp < 2; ntp++) {
                int nb = wn * 32 + ntp * 16;
                uint32_t addr = bb +
                    (uint32_t)((nb + b_key8 + krow) * GP2 + kk * 16 + b_dim8) * 2;
                uint32_t b0, b1, b2, b3;
                ldsm_x4(b0, b1, b2, b3, addr);
                uint32_t blo[2] = {b0, b1}, bhi[2] = {b2, b3};
#pragma unroll
                for (int mt = 0; mt < 2; mt++) {
                    mma_f16(acc[mt][2 * ntp],     a[mt], blo);
                    mma_f16(acc[mt][2 * ntp + 1], a[mt], bhi);
                }
            }
        }
        __syncthreads();
    }
    epi(acc);
}

// ---------------------------------------------------------------------------
// Fused QKV projection (grid.x = 24 col-tiles over [Q | K | V]).
// ---------------------------------------------------------------------------
__global__ __launch_bounds__(256) void gemm_qkv(const __half* __restrict__ X,
                                                const __half* __restrict__ Wq,
                                                const __half* __restrict__ Wk,
                                                const __half* __restrict__ Wv,
                                                __half* __restrict__ Oq,
                                                __half* __restrict__ Ok,
                                                __half* __restrict__ Ov,
                                                const float* __restrict__ cosb,
                                                const float* __restrict__ sinb) {
    const int tid = threadIdx.x;
    const int wid = tid >> 5;
    const int lane = tid & 31;
    const int g = lane >> 2;
    const int c = lane & 3;
    const int wm = wid >> 1;
    const int wn = wid & 1;
    const int row0 = blockIdx.y * 128;
    const int col0 = blockIdx.x * 64;

    const __half* Bp; __half* Cp; int bc, Nn; bool rope; float alpha;
    if (col0 < DIM)              { Bp = Wq; Cp = Oq; bc = col0;               Nn = DIM;   rope = true;  alpha = 0.125f * LOG2E; }
    else if (col0 < DIM + KVDIM) { Bp = Wk; Cp = Ok; bc = col0 - DIM;         Nn = KVDIM; rope = true;  alpha = 1.0f; }
    else                         { Bp = Wv; Cp = Ov; bc = col0 - DIM - KVDIM; Nn = KVDIM; rope = false; alpha = 1.0f; }

    gemm_core(X, Bp, row0, bc, DIM, [&](float acc[2][4][4]) {
#pragma unroll
        for (int mt = 0; mt < 2; mt++) {
#pragma unroll
            for (int nt = 0; nt < 4; nt++) {
                int r = row0 + wm * 32 + mt * 16 + g;
                int cc = bc + wn * 32 + nt * 8 + 2 * c;
                float v0 = acc[mt][nt][0] * alpha;
                float v1 = acc[mt][nt][1] * alpha;
                float v2 = acc[mt][nt][2] * alpha;
                float v3 = acc[mt][nt][3] * alpha;
                if (rope) {
                    int i = (cc & 63) >> 1;
                    float c0 = cosb[r * 32 + i],       s0 = sinb[r * 32 + i];
                    float c1 = cosb[(r + 8) * 32 + i], s1 = sinb[(r + 8) * 32 + i];
                    float t0 = v0 * c0 - v1 * s0;
                    float t1 = v0 * s0 + v1 * c0;
                    float t2 = v2 * c1 - v3 * s1;
                    float t3 = v2 * s1 + v3 * c1;
                    v0 = t0; v1 = t1; v2 = t2; v3 = t3;
                }
                *(uint32_t*)&Cp[(size_t)r * Nn + cc]       = pack_h2(v0, v1);
                *(uint32_t*)&Cp[(size_t)(r + 8) * Nn + cc] = pack_h2(v2, v3);
            }
        }
    });
}

// ---------------------------------------------------------------------------
// O-projection: fp16 A,B -> fp32 C.
// ---------------------------------------------------------------------------
__global__ __launch_bounds__(256) void gemm_o(const __half* __restrict__ A,
                                              const __half* __restrict__ B,
                                              float* __restrict__ C) {
    const int tid = threadIdx.x;
    const int wid = tid >> 5;
    const int lane = tid & 31;
    const int g = lane >> 2;
    const int c = lane & 3;
    const int wm = wid >> 1;
    const int wn = wid & 1;
    const int row0 = blockIdx.y * 128;
    const int col0 = blockIdx.x * 64;

    gemm_core(A, B, row0, col0, DIM, [&](float acc[2][4][4]) {
#pragma unroll
        for (int mt = 0; mt < 2; mt++) {
#pragma unroll
            for (int nt = 0; nt < 4; nt++) {
                int r = row0 + wm * 32 + mt * 16 + g;
                int col = col0 + wn * 32 + nt * 8 + 2 * c;
                *(float2*)&C[(size_t)r * DIM + col] =
                    make_float2(acc[mt][nt][0], acc[mt][nt][1]);
                *(float2*)&C[(size_t)(r + 8) * DIM + col] =
                    make_float2(acc[mt][nt][2], acc[mt][nt][3]);
            }
        }
    });
}

// ---------------------------------------------------------------------------
// Flash attention (unchanged from R14): f16 mma, causal, GQA, exp2 softmax,
// 128-row q-tiles, 128-key cp.async stages, register P/Q fragments.
// ---------------------------------------------------------------------------
#define FP 72
#define FL_QS 0
#define FL_K0 (128 * FP)
#define FL_V0 (FL_K0 + 128 * FP)
#define KVBUF (256 * FP)
#define FLASH_SMEM ((128 * FP + 2 * KVBUF) * 2)

__global__ __launch_bounds__(256) void flash_f16(const __half* __restrict__ Q,
                                                 const __half* __restrict__ K,
                                                 const __half* __restrict__ V,
                                                 __half* __restrict__ O) {
    __half* Qs = fsm + FL_QS;

    const int qt = gridDim.x - 1 - blockIdx.x;
    const int h  = blockIdx.y;
    const int kvh = h >> 2;
    const int tid = threadIdx.x;
    const int w = tid >> 5;
    const int lane = tid & 31;
    const int g = lane >> 2;
    const int c = lane & 3;
    const int q0 = qt * 128;
    const int qb = w * 16;

    const uint32_t sbase = smem_u32(fsm);
    const int lm_row = lane & 15;
    const int lm_cs  = (lane >> 4) & 1;
    const int km = lane >> 3;
    const int krow = lane & 7;
    const int k_key8 = (km >> 1) << 3;
    const int k_dim8 = (km & 1) << 3;

    const int NT = qt + 1;

    auto load_kv = [&](int kt, int buf) {
        const int k0 = kt * 128;
        uint32_t kb = sbase + (uint32_t)(FL_K0 + buf * KVBUF) * 2;
        uint32_t vb = sbase + (uint32_t)(FL_V0 + buf * KVBUF) * 2;
#pragma unroll
        for (int i = 0; i < 4; i++) {
            int lin = tid + 256 * i;
            int r  = lin >> 3;
            int d8 = (lin & 7) << 3;
            uint32_t off = (uint32_t)(r * FP + d8) * 2;
            cp16(kb + off, &K[(size_t)(k0 + r) * KVDIM + kvh * HD + d8]);
            cp16(vb + off, &V[(size_t)(k0 + r) * KVDIM + kvh * HD + d8]);
        }
        CP_COMMIT();
    };

#pragma unroll
    for (int i = 0; i < 4; i++) {
        int lin = tid + 256 * i;
        int r  = lin >> 3;
        int d8 = (lin & 7) << 3;
        *(uint4*)&Qs[r * FP + d8] =
            *(const uint4*)&Q[(size_t)(q0 + r) * DIM + h * HD + d8];
    }
    load_kv(0, 0);
    __syncthreads();

    uint32_t qf[4][4];
#pragma unroll
    for (int kk = 0; kk < 4; kk++) {
        qf[kk][0] = *(uint32_t*)&Qs[(qb + g)     * FP + kk * 16 + 2 * c];
        qf[kk][1] = *(uint32_t*)&Qs[(qb + g + 8) * FP + kk * 16 + 2 * c];
        qf[kk][2] = *(uint32_t*)&Qs[(qb + g)     * FP + kk * 16 + 2 * c + 8];
        qf[kk][3] = *(uint32_t*)&Qs[(qb + g + 8) * FP + kk * 16 + 2 * c + 8];
    }

    float m0 = -1e30f, m1 = -1e30f, l0 = 0.f, l1 = 0.f;
    float oacc[8][4] = {};

    for (int kt = 0; kt < NT; kt++) {
        const int buf = kt & 1;
        cp_wait<0>();
        __syncthreads();

        if (kt + 1 < NT) load_kv(kt + 1, buf ^ 1);

#pragma unroll
        for (int half = 0; half < 2; half++) {
            const int k0 = kt * 128 + half * 64;
            if (k0 > q0 + qb + 15) continue;

            const uint32_t kbyte = sbase +
                (uint32_t)(FL_K0 + buf * KVBUF + half * 64 * FP) * 2;
            const uint32_t vbyte = sbase +
                (uint32_t)(FL_V0 + buf * KVBUF + half * 64 * FP) * 2;

            float s[8][4] = {};
#pragma unroll
            for (int kk = 0; kk < 4; kk++) {
#pragma unroll
                for (int ntp = 0; ntp < 4; ntp++) {
                    uint32_t addr = kbyte +
                        (uint32_t)((ntp * 16 + k_key8 + krow) * FP +
                                   kk * 16 + k_dim8) * 2;
                    uint32_t b0, b1, b2, b3;
                    ldsm_x4(b0, b1, b2, b3, addr);
                    uint32_t blo[2] = {b0, b1}, bhi[2] = {b2, b3};
                    mma_f16(s[2 * ntp],     qf[kk], blo);
                    mma_f16(s[2 * ntp + 1], qf[kk], bhi);
                }
            }

            if (k0 + 63 > q0 + qb) {
                int r0 = q0 + qb + g, r1 = r0 + 8;
#pragma unroll
                for (int nt = 0; nt < 8; nt++) {
                    int col = k0 + nt * 8 + 2 * c;
                    if (col     > r0) s[nt][0] = -1e30f;
                    if (col + 1 > r0) s[nt][1] = -1e30f;
                    if (col     > r1) s[nt][2] = -1e30f;
                    if (col + 1 > r1) s[nt][3] = -1e30f;
                }
            }

            float mx0 = -1e30f, mx1 = -1e30f;
#pragma unroll
            for (int nt = 0; nt < 8; nt++) {
                mx0 = fmaxf(mx0, fmaxf(s[nt][0], s[nt][1]));
                mx1 = fmaxf(mx1, fmaxf(s[nt][2], s[nt][3]));
            }
            mx0 = fmaxf(mx0, __shfl_xor_sync(0xffffffffu, mx0, 1));
            mx0 = fmaxf(mx0, __shfl_xor_sync(0xffffffffu, mx0, 2));
            mx1 = fmaxf(mx1, __shfl_xor_sync(0xffffffffu, mx1, 1));
            mx1 = fmaxf(mx1, __shfl_xor_sync(0xffffffffu, mx1, 2));

            float mn0 = fmaxf(m0, mx0), mn1 = fmaxf(m1, mx1);
            float al0 = exp2f(m0 - mn0), al1 = exp2f(m1 - mn1);
            float sum0 = 0.f, sum1 = 0.f;
#pragma unroll
            for (int nt = 0; nt < 8; nt++) {
                s[nt][0] = exp2f(s[nt][0] - mn0);
                s[nt][1] = exp2f(s[nt][1] - mn0);
                s[nt][2] = exp2f(s[nt][2] - mn1);
                s[nt][3] = exp2f(s[nt][3] - mn1);
                sum0 += s[nt][0] + s[nt][1];
                sum1 += s[nt][2] + s[nt][3];
            }
            sum0 += __shfl_xor_sync(0xffffffffu, sum0, 1);
            sum0 += __shfl_xor_sync(0xffffffffu, sum0, 2);
            sum1 += __shfl_xor_sync(0xffffffffu, sum1, 1);
            sum1 += __shfl_xor_sync(0xffffffffu, sum1, 2);
            l0 = l0 * al0 + sum0;  m0 = mn0;
            l1 = l1 * al1 + sum1;  m1 = mn1;
#pragma unroll
            for (int nt = 0; nt < 8; nt++) {
                oacc[nt][0] *= al0; oacc[nt][1] *= al0;
                oacc[nt][2] *= al1; oacc[nt][3] *= al1;
            }

#pragma unroll
            for (int kk = 0; kk < 4; kk++) {
                uint32_t a[4];
                a[0] = pack_h2(s[2 * kk][0],     s[2 * kk][1]);
                a[1] = pack_h2(s[2 * kk][2],     s[2 * kk][3]);
                a[2] = pack_h2(s[2 * kk + 1][0], s[2 * kk + 1][1]);
                a[3] = pack_h2(s[2 * kk + 1][2], s[2 * kk + 1][3]);
#pragma unroll
                for (int ntp = 0; ntp < 4; ntp++) {
                    uint32_t addr = vbyte +
                        (uint32_t)(kk * 16 + lm_row) * (FP * 2) +
                        (uint32_t)(16 * ntp + 8 * lm_cs) * 2;
                    uint32_t b0, b1, b2, b3;
                    ldsm_x4_trans(b0, b1, b2, b3, addr);
                    uint32_t blo[2] = {b0, b1}, bhi[2] = {b2, b3};
                    mma_f16(oacc[2 * ntp],     a, blo);
                    mma_f16(oacc[2 * ntp + 1], a, bhi);
                }
            }
        }
    }

    float inv0 = 1.f / l0, inv1 = 1.f / l1;
    int r0 = q0 + qb + g;
#pragma unroll
    for (int nt = 0; nt < 8; nt++) {
        int col = h * HD + nt * 8 + 2 * c;
        *(uint32_t*)&O[(size_t)r0 * DIM + col] =
            pack_h2(oacc[nt][0] * inv0, oacc[nt][1] * inv0);
        *(uint32_t*)&O[(size_t)(r0 + 8) * DIM + col] =
            pack_h2(oacc[nt][2] * inv1, oacc[nt][3] * inv1);
    }
}

// ---------------------------------------------------------------------------
// Launch
// ---------------------------------------------------------------------------
extern "C" void kernel_launch(void* const* d_in, const int* in_sizes, int n_in,
                              void* d_out, int out_size) {
    const float* x  = (const float*)d_in[0];
    const float* fc = (const float*)d_in[1];
    const float* fs = (const float*)d_in[2];
    const float* wq = (const float*)d_in[3];
    const float* wk = (const float*)d_in[4];
    const float* wv = (const float*)d_in[5];
    const float* wo = (const float*)d_in[6];
    float* out = (float*)d_out;

    static __half *pq = nullptr, *pk, *pv, *pa, *px, *pwq, *pwk, *pwv, *pwo;
    if (!pq) {
        cudaGetSymbolAddress((void**)&pq,  g_qh);
        cudaGetSymbolAddress((void**)&pk,  g_kh);
        cudaGetSymbolAddress((void**)&pv,  g_vh);
        cudaGetSymbolAddress((void**)&pa,  g_ah);
        cudaGetSymbolAddress((void**)&px,  g_xh);
        cudaGetSymbolAddress((void**)&pwq, g_wqh);
        cudaGetSymbolAddress((void**)&pwk, g_wkh);
        cudaGetSymbolAddress((void**)&pwv, g_wvh);
        cudaGetSymbolAddress((void**)&pwo, g_woh);
        cudaFuncSetAttribute(flash_f16,
                             cudaFuncAttributeMaxDynamicSharedMemorySize,
                             FLASH_SMEM);
        cudaFuncSetAttribute(gemm_qkv,
                             cudaFuncAttributeMaxDynamicSharedMemorySize,
                             GEMM_SMEM);
        cudaFuncSetAttribute(gemm_o,
                             cudaFuncAttributeMaxDynamicSharedMemorySize,
                             GEMM_SMEM);
    }

    // Single fused fp32->fp16 prepass.
    cvt_all<<<(N4_TOT + 255) / 256, 256>>>(
        (const float4*)x,  (uint2*)px,
        (const float4*)wq, (uint2*)pwq,
        (const float4*)wk, (uint2*)pwk,
        (const float4*)wv, (uint2*)pwv,
        (const float4*)wo, (uint2*)pwo);

    dim3 blk(256);
    // Fused QKV projection (768 blocks), rope + scaling in epilogue.
    gemm_qkv<<<dim3((DIM + 2 * KVDIM) / 64, SEQ / 128), blk, GEMM_SMEM>>>(
        px, pwq, pwk, pwv, pq, pk, pv, fc, fs);

    // Flash attention.
    flash_f16<<<dim3(SEQ / 128, NHEADS), blk, FLASH_SMEM>>>(pq, pk, pv, pa);

    // O projection.
    gemm_o<<<dim3(DIM / 64, SEQ / 128), blk, GEMM_SMEM>>>(pa, pwo, out);
}

// round 16
// speedup vs baseline: 1.4853x; 1.0238x over previous
#include <cuda_runtime.h>
#include <cuda_fp16.h>
#include <stdint.h>
#include <math.h>

#define SEQ     4096
#define DIM     1024
#define NHEADS  16
#define NKV     4
#define HD      64
#define KVDIM   256
#define LOG2E   1.44269504088896f

// ---------------------------------------------------------------------------
// Scratch (device globals; cudaMalloc forbidden) — fp16
// ---------------------------------------------------------------------------
__device__ __half g_qh[SEQ * DIM];
__device__ __half g_kh[SEQ * KVDIM];
__device__ __half g_vh[SEQ * KVDIM];
__device__ __half g_ah[SEQ * DIM];
__device__ __half g_xh[SEQ * DIM];
__device__ __half g_wqh[DIM * DIM];
__device__ __half g_wkh[KVDIM * DIM];
__device__ __half g_wvh[KVDIM * DIM];
__device__ __half g_woh[DIM * DIM];

// ---------------------------------------------------------------------------
// Helpers
// ---------------------------------------------------------------------------
__device__ __forceinline__ uint32_t pack_h2(float a, float b) {
    __half2 h = __floats2half2_rn(a, b);
    return *(uint32_t*)&h;
}
// exp2 of two floats -> packed fp16x2 (single MUFU op on the half2 path)
__device__ __forceinline__ uint32_t h2exp2(float a, float b) {
    uint32_t h = pack_h2(a, b);
    uint32_t r;
    asm("ex2.approx.f16x2 %0, %1;" : "=r"(r) : "r"(h));
    return r;
}
__device__ __forceinline__ uint32_t smem_u32(const void* p) {
    uint32_t a;
    asm("{ .reg .u64 t; cvta.to.shared.u64 t, %1; cvt.u32.u64 %0, t; }"
        : "=r"(a) : "l"(p));
    return a;
}
__device__ __forceinline__ void mma_f16(float c[4], const uint32_t a[4],
                                        const uint32_t b[2]) {
    asm volatile(
        "mma.sync.aligned.m16n8k16.row.col.f32.f16.f16.f32 "
        "{%0,%1,%2,%3},{%4,%5,%6,%7},{%8,%9},{%0,%1,%2,%3};"
        : "+f"(c[0]), "+f"(c[1]), "+f"(c[2]), "+f"(c[3])
        : "r"(a[0]), "r"(a[1]), "r"(a[2]), "r"(a[3]), "r"(b[0]), "r"(b[1]));
}
__device__ __forceinline__ void ldsm_x4(uint32_t& r0, uint32_t& r1,
                                        uint32_t& r2, uint32_t& r3,
                                        uint32_t addr) {
    asm volatile(
        "ldmatrix.sync.aligned.m8n8.x4.shared.b16 {%0,%1,%2,%3}, [%4];"
        : "=r"(r0), "=r"(r1), "=r"(r2), "=r"(r3) : "r"(addr));
}
__device__ __forceinline__ void ldsm_x4_trans(uint32_t& r0, uint32_t& r1,
                                              uint32_t& r2, uint32_t& r3,
                                              uint32_t addr) {
    asm volatile(
        "ldmatrix.sync.aligned.m8n8.x4.trans.shared.b16 {%0,%1,%2,%3}, [%4];"
        : "=r"(r0), "=r"(r1), "=r"(r2), "=r"(r3) : "r"(addr));
}
__device__ __forceinline__ void cp16(uint32_t dst, const void* src) {
    asm volatile("cp.async.cg.shared.global [%0], [%1], 16;"
                 :: "r"(dst), "l"(src));
}
#define CP_COMMIT() asm volatile("cp.async.commit_group;" ::: "memory")
template <int N>
__device__ __forceinline__ void cp_wait() {
    asm volatile("cp.async.wait_group %0;" :: "n"(N) : "memory");
}

// ---------------------------------------------------------------------------
// Fused fp32 -> fp16 conversion prepass
// ---------------------------------------------------------------------------
#define N4_X   (SEQ * DIM / 4)
#define N4_WQ  (DIM * DIM / 4)
#define N4_WKV (KVDIM * DIM / 4)
#define N4_TOT (N4_X + N4_WQ + 2 * N4_WKV + N4_WQ)

__global__ void cvt_all(const float4* __restrict__ x,  uint2* __restrict__ xo,
                        const float4* __restrict__ wq, uint2* __restrict__ wqo,
                        const float4* __restrict__ wk, uint2* __restrict__ wko,
                        const float4* __restrict__ wv, uint2* __restrict__ wvo,
                        const float4* __restrict__ wo, uint2* __restrict__ woo) {
    int i = blockIdx.x * blockDim.x + threadIdx.x;
    if (i >= N4_TOT) return;
    const float4* src; uint2* dst; int j = i;
    if (j < N4_X)              { src = x;  dst = xo;  }
    else if ((j -= N4_X)  < N4_WQ)  { src = wq; dst = wqo; }
    else if ((j -= N4_WQ) < N4_WKV) { src = wk; dst = wko; }
    else if ((j -= N4_WKV) < N4_WKV){ src = wv; dst = wvo; }
    else { j -= N4_WKV;          src = wo; dst = woo; }
    float4 v = src[j];
    dst[j] = make_uint2(pack_h2(v.x, v.y), pack_h2(v.z, v.w));
}

// ---------------------------------------------------------------------------
// GEMM mainloop core (shared): BM=128, BN=64, BK=64, 256 thr, 2-stage
// cp.async, ldmatrix.x4 fragments. Dynamic smem 55296 B.
// ---------------------------------------------------------------------------
#define GP2   72
#define GA_ST (128 * GP2)
#define GB_ST (64 * GP2)
#define GEMM_SMEM ((2 * GA_ST + 2 * GB_ST) * 2)

extern __shared__ __half fsm[];

template <typename EPI>
__device__ __forceinline__ void gemm_core(const __half* __restrict__ A,
                                          const __half* __restrict__ Bp,
                                          int row0, int bc, int K, EPI epi) {
    const int tid = threadIdx.x;
    const int wid = tid >> 5;
    const int lane = tid & 31;
    const int wm = wid >> 1;
    const int wn = wid & 1;

    const uint32_t abase = smem_u32(fsm);
    const uint32_t bbase = abase + 2 * GA_ST * 2;

    const int km = lane >> 3;
    const int krow = lane & 7;
    const int a_row = ((km & 1) << 3) + krow;
    const int a_col = (km >> 1) << 3;
    const int b_key8 = (km >> 1) << 3;
    const int b_dim8 = (km & 1) << 3;

    auto load = [&](int i, int st) {
        int k0 = i * 64;
        uint32_t ab = abase + (uint32_t)st * (GA_ST * 2);
        uint32_t bb = bbase + (uint32_t)st * (GB_ST * 2);
#pragma unroll
        for (int j = 0; j < 4; j++) {
            int lin = tid + 256 * j;
            int r  = lin >> 3;
            int d8 = (lin & 7) << 3;
            cp16(ab + (uint32_t)(r * GP2 + d8) * 2,
                 &A[(size_t)(row0 + r) * K + k0 + d8]);
        }
#pragma unroll
        for (int j = 0; j < 2; j++) {
            int lin = tid + 256 * j;
            int r  = lin >> 3;
            int d8 = (lin & 7) << 3;
            cp16(bb + (uint32_t)(r * GP2 + d8) * 2,
                 &Bp[(size_t)(bc + r) * K + k0 + d8]);
        }
        CP_COMMIT();
    };

    float acc[2][4][4] = {};
    const int NI = K / 64;
    load(0, 0);

    for (int i = 0; i < NI; i++) {
        const int st = i & 1;
        if (i + 1 < NI) { load(i + 1, st ^ 1); cp_wait<1>(); }
        else           { cp_wait<0>(); }
        __syncthreads();

        const uint32_t ab = abase + (uint32_t)st * (GA_ST * 2);
        const uint32_t bb = bbase + (uint32_t)st * (GB_ST * 2);
#pragma unroll
        for (int kk = 0; kk < 4; kk++) {
            uint32_t a[2][4];
#pragma unroll
            for (int mt = 0; mt < 2; mt++) {
                int mb = wm * 32 + mt * 16;
                uint32_t addr = ab +
                    (uint32_t)((mb + a_row) * GP2 + kk * 16 + a_col) * 2;
                ldsm_x4(a[mt][0], a[mt][1], a[mt][2], a[mt][3], addr);
            }
#pragma unroll
            for (int ntp = 0; ntp < 2; ntp++) {
                int nb = wn * 32 + ntp * 16;
                uint32_t addr = bb +
                    (uint32_t)((nb + b_key8 + krow) * GP2 + kk * 16 + b_dim8) * 2;
                uint32_t b0, b1, b2, b3;
                ldsm_x4(b0, b1, b2, b3, addr);
                uint32_t blo[2] = {b0, b1}, bhi[2] = {b2, b3};
#pragma unroll
                for (int mt = 0; mt < 2; mt++) {
                    mma_f16(acc[mt][2 * ntp],     a[mt], blo);
                    mma_f16(acc[mt][2 * ntp + 1], a[mt], bhi);
                }
            }
        }
        __syncthreads();
    }
    epi(acc);
}

// ---------------------------------------------------------------------------
// Fused QKV projection
// ---------------------------------------------------------------------------
__global__ __launch_bounds__(256) void gemm_qkv(const __half* __restrict__ X,
                                                const __half* __restrict__ Wq,
                                                const __half* __restrict__ Wk,
                                                const __half* __restrict__ Wv,
                                                __half* __restrict__ Oq,
                                                __half* __restrict__ Ok,
                                                __half* __restrict__ Ov,
                                                const float* __restrict__ cosb,
                                                const float* __restrict__ sinb) {
    const int tid = threadIdx.x;
    const int wid = tid >> 5;
    const int lane = tid & 31;
    const int g = lane >> 2;
    const int c = lane & 3;
    const int wm = wid >> 1;
    const int wn = wid & 1;
    const int row0 = blockIdx.y * 128;
    const int col0 = blockIdx.x * 64;

    const __half* Bp; __half* Cp; int bc, Nn; bool rope; float alpha;
    if (col0 < DIM)              { Bp = Wq; Cp = Oq; bc = col0;               Nn = DIM;   rope = true;  alpha = 0.125f * LOG2E; }
    else if (col0 < DIM + KVDIM) { Bp = Wk; Cp = Ok; bc = col0 - DIM;         Nn = KVDIM; rope = true;  alpha = 1.0f; }
    else                         { Bp = Wv; Cp = Ov; bc = col0 - DIM - KVDIM; Nn = KVDIM; rope = false; alpha = 1.0f; }

    gemm_core(X, Bp, row0, bc, DIM, [&](float acc[2][4][4]) {
#pragma unroll
        for (int mt = 0; mt < 2; mt++) {
#pragma unroll
            for (int nt = 0; nt < 4; nt++) {
                int r = row0 + wm * 32 + mt * 16 + g;
                int cc = bc + wn * 32 + nt * 8 + 2 * c;
                float v0 = acc[mt][nt][0] * alpha;
                float v1 = acc[mt][nt][1] * alpha;
                float v2 = acc[mt][nt][2] * alpha;
                float v3 = acc[mt][nt][3] * alpha;
                if (rope) {
                    int i = (cc & 63) >> 1;
                    float c0 = cosb[r * 32 + i],       s0 = sinb[r * 32 + i];
                    float c1 = cosb[(r + 8) * 32 + i], s1 = sinb[(r + 8) * 32 + i];
                    float t0 = v0 * c0 - v1 * s0;
                    float t1 = v0 * s0 + v1 * c0;
                    float t2 = v2 * c1 - v3 * s1;
                    float t3 = v2 * s1 + v3 * c1;
                    v0 = t0; v1 = t1; v2 = t2; v3 = t3;
                }
                *(uint32_t*)&Cp[(size_t)r * Nn + cc]       = pack_h2(v0, v1);
                *(uint32_t*)&Cp[(size_t)(r + 8) * Nn + cc] = pack_h2(v2, v3);
            }
        }
    });
}

// ---------------------------------------------------------------------------
// O-projection: fp16 A,B -> fp32 C.
// ---------------------------------------------------------------------------
__global__ __launch_bounds__(256) void gemm_o(const __half* __restrict__ A,
                                              const __half* __restrict__ B,
                                              float* __restrict__ C) {
    const int tid = threadIdx.x;
    const int wid = tid >> 5;
    const int lane = tid & 31;
    const int g = lane >> 2;
    const int c = lane & 3;
    const int wm = wid >> 1;
    const int wn = wid & 1;
    const int row0 = blockIdx.y * 128;
    const int col0 = blockIdx.x * 64;

    gemm_core(A, B, row0, col0, DIM, [&](float acc[2][4][4]) {
#pragma unroll
        for (int mt = 0; mt < 2; mt++) {
#pragma unroll
            for (int nt = 0; nt < 4; nt++) {
                int r = row0 + wm * 32 + mt * 16 + g;
                int col = col0 + wn * 32 + nt * 8 + 2 * c;
                *(float2*)&C[(size_t)r * DIM + col] =
                    make_float2(acc[mt][nt][0], acc[mt][nt][1]);
                *(float2*)&C[(size_t)(r + 8) * DIM + col] =
                    make_float2(acc[mt][nt][2], acc[mt][nt][3]);
            }
        }
    });
}

// ---------------------------------------------------------------------------
// Flash attention: f16 mma, causal, GQA, exp2-domain softmax with
// ex2.approx.f16x2 P-fragments and ones-MMA row sums (no sum shuffles).
// 128-row q-tiles, 128-key cp.async stages, register Q/P fragments.
// ---------------------------------------------------------------------------
#define FP 72
#define FL_QS 0
#define FL_K0 (128 * FP)
#define FL_V0 (FL_K0 + 128 * FP)
#define KVBUF (256 * FP)
#define FLASH_SMEM ((128 * FP + 2 * KVBUF) * 2)

__global__ __launch_bounds__(256) void flash_f16(const __half* __restrict__ Q,
                                                 const __half* __restrict__ K,
                                                 const __half* __restrict__ V,
                                                 __half* __restrict__ O) {
    __half* Qs = fsm + FL_QS;

    const int qt = gridDim.x - 1 - blockIdx.x;
    const int h  = blockIdx.y;
    const int kvh = h >> 2;
    const int tid = threadIdx.x;
    const int w = tid >> 5;
    const int lane = tid & 31;
    const int g = lane >> 2;
    const int c = lane & 3;
    const int q0 = qt * 128;
    const int qb = w * 16;

    const uint32_t sbase = smem_u32(fsm);
    const int lm_row = lane & 15;
    const int lm_cs  = (lane >> 4) & 1;
    const int km = lane >> 3;
    const int krow = lane & 7;
    const int k_key8 = (km >> 1) << 3;
    const int k_dim8 = (km & 1) << 3;

    const int NT = qt + 1;

    auto load_kv = [&](int kt, int buf) {
        const int k0 = kt * 128;
        uint32_t kb = sbase + (uint32_t)(FL_K0 + buf * KVBUF) * 2;
        uint32_t vb = sbase + (uint32_t)(FL_V0 + buf * KVBUF) * 2;
#pragma unroll
        for (int i = 0; i < 4; i++) {
            int lin = tid + 256 * i;
            int r  = lin >> 3;
            int d8 = (lin & 7) << 3;
            uint32_t off = (uint32_t)(r * FP + d8) * 2;
            cp16(kb + off, &K[(size_t)(k0 + r) * KVDIM + kvh * HD + d8]);
            cp16(vb + off, &V[(size_t)(k0 + r) * KVDIM + kvh * HD + d8]);
        }
        CP_COMMIT();
    };

#pragma unroll
    for (int i = 0; i < 4; i++) {
        int lin = tid + 256 * i;
        int r  = lin >> 3;
        int d8 = (lin & 7) << 3;
        *(uint4*)&Qs[r * FP + d8] =
            *(const uint4*)&Q[(size_t)(q0 + r) * DIM + h * HD + d8];
    }
    load_kv(0, 0);
    __syncthreads();

    uint32_t qf[4][4];
#pragma unroll
    for (int kk = 0; kk < 4; kk++) {
        qf[kk][0] = *(uint32_t*)&Qs[(qb + g)     * FP + kk * 16 + 2 * c];
        qf[kk][1] = *(uint32_t*)&Qs[(qb + g + 8) * FP + kk * 16 + 2 * c];
        qf[kk][2] = *(uint32_t*)&Qs[(qb + g)     * FP + kk * 16 + 2 * c + 8];
        qf[kk][3] = *(uint32_t*)&Qs[(qb + g + 8) * FP + kk * 16 + 2 * c + 8];
    }

    float m0 = -1e30f, m1 = -1e30f, l0 = 0.f, l1 = 0.f;
    float oacc[8][4] = {};
    const uint32_t ones2[2] = {0x3C003C00u, 0x3C003C00u};   // fp16 1.0 x4

    for (int kt = 0; kt < NT; kt++) {
        const int buf = kt & 1;
        cp_wait<0>();
        __syncthreads();

        if (kt + 1 < NT) load_kv(kt + 1, buf ^ 1);

#pragma unroll
        for (int half = 0; half < 2; half++) {
            const int k0 = kt * 128 + half * 64;
            if (k0 > q0 + qb + 15) continue;

            const uint32_t kbyte = sbase +
                (uint32_t)(FL_K0 + buf * KVBUF + half * 64 * FP) * 2;
            const uint32_t vbyte = sbase +
                (uint32_t)(FL_V0 + buf * KVBUF + half * 64 * FP) * 2;

            // S = Q K^T (log2 domain).
            float s[8][4] = {};
#pragma unroll
            for (int kk = 0; kk < 4; kk++) {
#pragma unroll
                for (int ntp = 0; ntp < 4; ntp++) {
                    uint32_t addr = kbyte +
                        (uint32_t)((ntp * 16 + k_key8 + krow) * FP +
                                   kk * 16 + k_dim8) * 2;
                    uint32_t b0, b1, b2, b3;
                    ldsm_x4(b0, b1, b2, b3, addr);
                    uint32_t blo[2] = {b0, b1}, bhi[2] = {b2, b3};
                    mma_f16(s[2 * ntp],     qf[kk], blo);
                    mma_f16(s[2 * ntp + 1], qf[kk], bhi);
                }
            }

            if (k0 + 63 > q0 + qb) {
                int r0 = q0 + qb + g, r1 = r0 + 8;
#pragma unroll
                for (int nt = 0; nt < 8; nt++) {
                    int col = k0 + nt * 8 + 2 * c;
                    if (col     > r0) s[nt][0] = -1e30f;
                    if (col + 1 > r0) s[nt][1] = -1e30f;
                    if (col     > r1) s[nt][2] = -1e30f;
                    if (col + 1 > r1) s[nt][3] = -1e30f;
                }
            }

            // Row max (only remaining shuffle reduction).
            float mx0 = -1e30f, mx1 = -1e30f;
#pragma unroll
            for (int nt = 0; nt < 8; nt++) {
                mx0 = fmaxf(mx0, fmaxf(s[nt][0], s[nt][1]));
                mx1 = fmaxf(mx1, fmaxf(s[nt][2], s[nt][3]));
            }
            mx0 = fmaxf(mx0, __shfl_xor_sync(0xffffffffu, mx0, 1));
            mx0 = fmaxf(mx0, __shfl_xor_sync(0xffffffffu, mx0, 2));
            mx1 = fmaxf(mx1, __shfl_xor_sync(0xffffffffu, mx1, 1));
            mx1 = fmaxf(mx1, __shfl_xor_sync(0xffffffffu, mx1, 2));

            float mn0 = fmaxf(m0, mx0), mn1 = fmaxf(m1, mx1);
            float al0 = exp2f(m0 - mn0), al1 = exp2f(m1 - mn1);

            // P A-fragments directly via fp16x2 exp2 (masked -> -inf -> 0).
            uint32_t pa[4][4];
#pragma unroll
            for (int kk = 0; kk < 4; kk++) {
                pa[kk][0] = h2exp2(s[2 * kk][0] - mn0,     s[2 * kk][1] - mn0);
                pa[kk][1] = h2exp2(s[2 * kk][2] - mn1,     s[2 * kk][3] - mn1);
                pa[kk][2] = h2exp2(s[2 * kk + 1][0] - mn0, s[2 * kk + 1][1] - mn0);
                pa[kk][3] = h2exp2(s[2 * kk + 1][2] - mn1, s[2 * kk + 1][3] - mn1);
            }

            // Row sums via ones-MMA: every output column = row sum.
            float sacc[4] = {};
#pragma unroll
            for (int kk = 0; kk < 4; kk++)
                mma_f16(sacc, pa[kk], ones2);

            l0 = l0 * al0 + sacc[0];  m0 = mn0;
            l1 = l1 * al1 + sacc[2];  m1 = mn1;
#pragma unroll
            for (int nt = 0; nt < 8; nt++) {
                oacc[nt][0] *= al0; oacc[nt][1] *= al0;
                oacc[nt][2] *= al1; oacc[nt][3] *= al1;
            }

            // O += P V.
#pragma unroll
            for (int kk = 0; kk < 4; kk++) {
#pragma unroll
                for (int ntp = 0; ntp < 4; ntp++) {
                    uint32_t addr = vbyte +
                        (uint32_t)(kk * 16 + lm_row) * (FP * 2) +
                        (uint32_t)(16 * ntp + 8 * lm_cs) * 2;
                    uint32_t b0, b1, b2, b3;
                    ldsm_x4_trans(b0, b1, b2, b3, addr);
                    uint32_t blo[2] = {b0, b1}, bhi[2] = {b2, b3};
                    mma_f16(oacc[2 * ntp],     pa[kk], blo);
                    mma_f16(oacc[2 * ntp + 1], pa[kk], bhi);
                }
            }
        }
    }

    float inv0 = 1.f / l0, inv1 = 1.f / l1;
    int r0 = q0 + qb + g;
#pragma unroll
    for (int nt = 0; nt < 8; nt++) {
        int col = h * HD + nt * 8 + 2 * c;
        *(uint32_t*)&O[(size_t)r0 * DIM + col] =
            pack_h2(oacc[nt][0] * inv0, oacc[nt][1] * inv0);
        *(uint32_t*)&O[(size_t)(r0 + 8) * DIM + col] =
            pack_h2(oacc[nt][2] * inv1, oacc[nt][3] * inv1);
    }
}

// ---------------------------------------------------------------------------
// Launch
// ---------------------------------------------------------------------------
extern "C" void kernel_launch(void* const* d_in, const int* in_sizes, int n_in,
                              void* d_out, int out_size) {
    const float* x  = (const float*)d_in[0];
    const float* fc = (const float*)d_in[1];
    const float* fs = (const float*)d_in[2];
    const float* wq = (const float*)d_in[3];
    const float* wk = (const float*)d_in[4];
    const float* wv = (const float*)d_in[5];
    const float* wo = (const float*)d_in[6];
    float* out = (float*)d_out;

    static __half *pq = nullptr, *pk, *pv, *pa, *px, *pwq, *pwk, *pwv, *pwo;
    if (!pq) {
        cudaGetSymbolAddress((void**)&pq,  g_qh);
        cudaGetSymbolAddress((void**)&pk,  g_kh);
        cudaGetSymbolAddress((void**)&pv,  g_vh);
        cudaGetSymbolAddress((void**)&pa,  g_ah);
        cudaGetSymbolAddress((void**)&px,  g_xh);
        cudaGetSymbolAddress((void**)&pwq, g_wqh);
        cudaGetSymbolAddress((void**)&pwk, g_wkh);
        cudaGetSymbolAddress((void**)&pwv, g_wvh);
        cudaGetSymbolAddress((void**)&pwo, g_woh);
        cudaFuncSetAttribute(flash_f16,
                             cudaFuncAttributeMaxDynamicSharedMemorySize,
                             FLASH_SMEM);
        cudaFuncSetAttribute(gemm_qkv,
                             cudaFuncAttributeMaxDynamicSharedMemorySize,
                             GEMM_SMEM);
        cudaFuncSetAttribute(gemm_o,
                             cudaFuncAttributeMaxDynamicSharedMemorySize,
                             GEMM_SMEM);
    }

    cvt_all<<<(N4_TOT + 255) / 256, 256>>>(
        (const float4*)x,  (uint2*)px,
        (const float4*)wq, (uint2*)pwq,
        (const float4*)wk, (uint2*)pwk,
        (const float4*)wv, (uint2*)pwv,
        (const float4*)wo, (uint2*)pwo);

    dim3 blk(256);
    gemm_qkv<<<dim3((DIM + 2 * KVDIM) / 64, SEQ / 128), blk, GEMM_SMEM>>>(
        px, pwq, pwk, pwv, pq, pk, pv, fc, fs);

    flash_f16<<<dim3(SEQ / 128, NHEADS), blk, FLASH_SMEM>>>(pq, pk, pv, pa);

    gemm_o<<<dim3(DIM / 64, SEQ / 128), blk, GEMM_SMEM>>>(pa, pwo, out);
}

// round 17
// speedup vs baseline: 1.4946x; 1.0062x over previous
#include <cuda_runtime.h>
#include <cuda_fp16.h>
#include <stdint.h>
#include <math.h>

#define SEQ     4096
#define DIM     1024
#define NHEADS  16
#define NKV     4
#define HD      64
#define KVDIM   256
#define LOG2E   1.44269504088896f

// ---------------------------------------------------------------------------
// Scratch (device globals; cudaMalloc forbidden) — fp16
// ---------------------------------------------------------------------------
__device__ __half g_qh[SEQ * DIM];
__device__ __half g_kh[SEQ * KVDIM];
__device__ __half g_vh[SEQ * KVDIM];
__device__ __half g_ah[SEQ * DIM];
__device__ __half g_xh[SEQ * DIM];
__device__ __half g_wqh[DIM * DIM];
__device__ __half g_wkh[KVDIM * DIM];
__device__ __half g_wvh[KVDIM * DIM];
__device__ __half g_woh[DIM * DIM];

// ---------------------------------------------------------------------------
// Helpers
// ---------------------------------------------------------------------------
__device__ __forceinline__ uint32_t pack_h2(float a, float b) {
    __half2 h = __floats2half2_rn(a, b);
    return *(uint32_t*)&h;
}
__device__ __forceinline__ uint32_t h2exp2(float a, float b) {
    uint32_t h = pack_h2(a, b);
    uint32_t r;
    asm("ex2.approx.f16x2 %0, %1;" : "=r"(r) : "r"(h));
    return r;
}
__device__ __forceinline__ uint32_t smem_u32(const void* p) {
    uint32_t a;
    asm("{ .reg .u64 t; cvta.to.shared.u64 t, %1; cvt.u32.u64 %0, t; }"
        : "=r"(a) : "l"(p));
    return a;
}
__device__ __forceinline__ void mma_f16(float c[4], const uint32_t a[4],
                                        const uint32_t b[2]) {
    asm volatile(
        "mma.sync.aligned.m16n8k16.row.col.f32.f16.f16.f32 "
        "{%0,%1,%2,%3},{%4,%5,%6,%7},{%8,%9},{%0,%1,%2,%3};"
        : "+f"(c[0]), "+f"(c[1]), "+f"(c[2]), "+f"(c[3])
        : "r"(a[0]), "r"(a[1]), "r"(a[2]), "r"(a[3]), "r"(b[0]), "r"(b[1]));
}
__device__ __forceinline__ void ldsm_x4(uint32_t& r0, uint32_t& r1,
                                        uint32_t& r2, uint32_t& r3,
                                        uint32_t addr) {
    asm volatile(
        "ldmatrix.sync.aligned.m8n8.x4.shared.b16 {%0,%1,%2,%3}, [%4];"
        : "=r"(r0), "=r"(r1), "=r"(r2), "=r"(r3) : "r"(addr));
}
__device__ __forceinline__ void ldsm_x4_trans(uint32_t& r0, uint32_t& r1,
                                              uint32_t& r2, uint32_t& r3,
                                              uint32_t addr) {
    asm volatile(
        "ldmatrix.sync.aligned.m8n8.x4.trans.shared.b16 {%0,%1,%2,%3}, [%4];"
        : "=r"(r0), "=r"(r1), "=r"(r2), "=r"(r3) : "r"(addr));
}
__device__ __forceinline__ void cp16(uint32_t dst, const void* src) {
    asm volatile("cp.async.cg.shared.global [%0], [%1], 16;"
                 :: "r"(dst), "l"(src));
}
#define CP_COMMIT() asm volatile("cp.async.commit_group;" ::: "memory")
template <int N>
__device__ __forceinline__ void cp_wait() {
    asm volatile("cp.async.wait_group %0;" :: "n"(N) : "memory");
}

// ---------------------------------------------------------------------------
// Fused fp32 -> fp16 conversion prepass
// ---------------------------------------------------------------------------
#define N4_X   (SEQ * DIM / 4)
#define N4_WQ  (DIM * DIM / 4)
#define N4_WKV (KVDIM * DIM / 4)
#define N4_TOT (N4_X + N4_WQ + 2 * N4_WKV + N4_WQ)

__global__ void cvt_all(const float4* __restrict__ x,  uint2* __restrict__ xo,
                        const float4* __restrict__ wq, uint2* __restrict__ wqo,
                        const float4* __restrict__ wk, uint2* __restrict__ wko,
                        const float4* __restrict__ wv, uint2* __restrict__ wvo,
                        const float4* __restrict__ wo, uint2* __restrict__ woo) {
    int i = blockIdx.x * blockDim.x + threadIdx.x;
    if (i >= N4_TOT) return;
    const float4* src; uint2* dst; int j = i;
    if (j < N4_X)              { src = x;  dst = xo;  }
    else if ((j -= N4_X)  < N4_WQ)  { src = wq; dst = wqo; }
    else if ((j -= N4_WQ) < N4_WKV) { src = wk; dst = wko; }
    else if ((j -= N4_WKV) < N4_WKV){ src = wv; dst = wvo; }
    else { j -= N4_WKV;          src = wo; dst = woo; }
    float4 v = src[j];
    dst[j] = make_uint2(pack_h2(v.x, v.y), pack_h2(v.z, v.w));
}

// ---------------------------------------------------------------------------
// GEMM mainloop core: BM=128, BN=64, BK=64, 256 thr, 2-stage cp.async,
// ldmatrix.x4 fragments, SINGLE-sync mainloop (flash-style):
//   cp_wait<0> -> sync -> issue load(i+1) -> compute(i)
// Hazards: load(i+1) writes buf^1, last read in compute(i-1); all warps
// passed this iteration's sync after that compute. cp_wait<0> at loop top
// has only group(i) outstanding. Dynamic smem 55296 B (3 CTAs/SM).
// ---------------------------------------------------------------------------
#define GP2   72
#define GA_ST (128 * GP2)
#define GB_ST (64 * GP2)
#define GEMM_SMEM ((2 * GA_ST + 2 * GB_ST) * 2)

extern __shared__ __half fsm[];

template <typename EPI>
__device__ __forceinline__ void gemm_core(const __half* __restrict__ A,
                                          const __half* __restrict__ Bp,
                                          int row0, int bc, int K, EPI epi) {
    const int tid = threadIdx.x;
    const int wid = tid >> 5;
    const int lane = tid & 31;
    const int wm = wid >> 1;
    const int wn = wid & 1;

    const uint32_t abase = smem_u32(fsm);
    const uint32_t bbase = abase + 2 * GA_ST * 2;

    const int km = lane >> 3;
    const int krow = lane & 7;
    const int a_row = ((km & 1) << 3) + krow;
    const int a_col = (km >> 1) << 3;
    const int b_key8 = (km >> 1) << 3;
    const int b_dim8 = (km & 1) << 3;

    auto load = [&](int i, int st) {
        int k0 = i * 64;
        uint32_t ab = abase + (uint32_t)st * (GA_ST * 2);
        uint32_t bb = bbase + (uint32_t)st * (GB_ST * 2);
#pragma unroll
        for (int j = 0; j < 4; j++) {
            int lin = tid + 256 * j;
            int r  = lin >> 3;
            int d8 = (lin & 7) << 3;
            cp16(ab + (uint32_t)(r * GP2 + d8) * 2,
                 &A[(size_t)(row0 + r) * K + k0 + d8]);
        }
#pragma unroll
        for (int j = 0; j < 2; j++) {
            int lin = tid + 256 * j;
            int r  = lin >> 3;
            int d8 = (lin & 7) << 3;
            cp16(bb + (uint32_t)(r * GP2 + d8) * 2,
                 &Bp[(size_t)(bc + r) * K + k0 + d8]);
        }
        CP_COMMIT();
    };

    float acc[2][4][4] = {};
    const int NI = K / 64;
    load(0, 0);

    for (int i = 0; i < NI; i++) {
        const int st = i & 1;
        cp_wait<0>();
        __syncthreads();
        if (i + 1 < NI) load(i + 1, st ^ 1);

        const uint32_t ab = abase + (uint32_t)st * (GA_ST * 2);
        const uint32_t bb = bbase + (uint32_t)st * (GB_ST * 2);
#pragma unroll
        for (int kk = 0; kk < 4; kk++) {
            uint32_t a[2][4];
#pragma unroll
            for (int mt = 0; mt < 2; mt++) {
                int mb = wm * 32 + mt * 16;
                uint32_t addr = ab +
                    (uint32_t)((mb + a_row) * GP2 + kk * 16 + a_col) * 2;
                ldsm_x4(a[mt][0], a[mt][1], a[mt][2], a[mt][3], addr);
            }
#pragma unroll
            for (int ntp = 0; ntp < 2; ntp++) {
                int nb = wn * 32 + ntp * 16;
                uint32_t addr = bb +
                    (uint32_t)((nb + b_key8 + krow) * GP2 + kk * 16 + b_dim8) * 2;
                uint32_t b0, b1, b2, b3;
                ldsm_x4(b0, b1, b2, b3, addr);
                uint32_t blo[2] = {b0, b1}, bhi[2] = {b2, b3};
#pragma unroll
                for (int mt = 0; mt < 2; mt++) {
                    mma_f16(acc[mt][2 * ntp],     a[mt], blo);
                    mma_f16(acc[mt][2 * ntp + 1], a[mt], bhi);
                }
            }
        }
    }
    epi(acc);
}

// ---------------------------------------------------------------------------
// Fused QKV projection
// ---------------------------------------------------------------------------
__global__ __launch_bounds__(256) void gemm_qkv(const __half* __restrict__ X,
                                                const __half* __restrict__ Wq,
                                                const __half* __restrict__ Wk,
                                                const __half* __restrict__ Wv,
                                                __half* __restrict__ Oq,
                                                __half* __restrict__ Ok,
                                                __half* __restrict__ Ov,
                                                const float* __restrict__ cosb,
                                                const float* __restrict__ sinb) {
    const int tid = threadIdx.x;
    const int wid = tid >> 5;
    const int lane = tid & 31;
    const int g = lane >> 2;
    const int c = lane & 3;
    const int wm = wid >> 1;
    const int wn = wid & 1;
    const int row0 = blockIdx.y * 128;
    const int col0 = blockIdx.x * 64;

    const __half* Bp; __half* Cp; int bc, Nn; bool rope; float alpha;
    if (col0 < DIM)              { Bp = Wq; Cp = Oq; bc = col0;               Nn = DIM;   rope = true;  alpha = 0.125f * LOG2E; }
    else if (col0 < DIM + KVDIM) { Bp = Wk; Cp = Ok; bc = col0 - DIM;         Nn = KVDIM; rope = true;  alpha = 1.0f; }
    else                         { Bp = Wv; Cp = Ov; bc = col0 - DIM - KVDIM; Nn = KVDIM; rope = false; alpha = 1.0f; }

    gemm_core(X, Bp, row0, bc, DIM, [&](float acc[2][4][4]) {
#pragma unroll
        for (int mt = 0; mt < 2; mt++) {
#pragma unroll
            for (int nt = 0; nt < 4; nt++) {
                int r = row0 + wm * 32 + mt * 16 + g;
                int cc = bc + wn * 32 + nt * 8 + 2 * c;
                float v0 = acc[mt][nt][0] * alpha;
                float v1 = acc[mt][nt][1] * alpha;
                float v2 = acc[mt][nt][2] * alpha;
                float v3 = acc[mt][nt][3] * alpha;
                if (rope) {
                    int i = (cc & 63) >> 1;
                    float c0 = cosb[r * 32 + i],       s0 = sinb[r * 32 + i];
                    float c1 = cosb[(r + 8) * 32 + i], s1 = sinb[(r + 8) * 32 + i];
                    float t0 = v0 * c0 - v1 * s0;
                    float t1 = v0 * s0 + v1 * c0;
                    float t2 = v2 * c1 - v3 * s1;
                    float t3 = v2 * s1 + v3 * c1;
                    v0 = t0; v1 = t1; v2 = t2; v3 = t3;
                }
                *(uint32_t*)&Cp[(size_t)r * Nn + cc]       = pack_h2(v0, v1);
                *(uint32_t*)&Cp[(size_t)(r + 8) * Nn + cc] = pack_h2(v2, v3);
            }
        }
    });
}

// ---------------------------------------------------------------------------
// O-projection: fp16 A,B -> fp32 C.
// ---------------------------------------------------------------------------
__global__ __launch_bounds__(256) void gemm_o(const __half* __restrict__ A,
                                              const __half* __restrict__ B,
                                              float* __restrict__ C) {
    const int tid = threadIdx.x;
    const int wid = tid >> 5;
    const int lane = tid & 31;
    const int g = lane >> 2;
    const int c = lane & 3;
    const int wm = wid >> 1;
    const int wn = wid & 1;
    const int row0 = blockIdx.y * 128;
    const int col0 = blockIdx.x * 64;

    gemm_core(A, B, row0, col0, DIM, [&](float acc[2][4][4]) {
#pragma unroll
        for (int mt = 0; mt < 2; mt++) {
#pragma unroll
            for (int nt = 0; nt < 4; nt++) {
                int r = row0 + wm * 32 + mt * 16 + g;
                int col = col0 + wn * 32 + nt * 8 + 2 * c;
                *(float2*)&C[(size_t)r * DIM + col] =
                    make_float2(acc[mt][nt][0], acc[mt][nt][1]);
                *(float2*)&C[(size_t)(r + 8) * DIM + col] =
                    make_float2(acc[mt][nt][2], acc[mt][nt][3]);
            }
        }
    });
}

// ---------------------------------------------------------------------------
// Flash attention (unchanged from R16): f16 mma, causal, GQA, exp2-domain
// softmax with ex2.approx.f16x2 P-fragments and ones-MMA row sums.
// ---------------------------------------------------------------------------
#define FP 72
#define FL_QS 0
#define FL_K0 (128 * FP)
#define FL_V0 (FL_K0 + 128 * FP)
#define KVBUF (256 * FP)
#define FLASH_SMEM ((128 * FP + 2 * KVBUF) * 2)

__global__ __launch_bounds__(256) void flash_f16(const __half* __restrict__ Q,
                                                 const __half* __restrict__ K,
                                                 const __half* __restrict__ V,
                                                 __half* __restrict__ O) {
    __half* Qs = fsm + FL_QS;

    const int qt = gridDim.x - 1 - blockIdx.x;
    const int h  = blockIdx.y;
    const int kvh = h >> 2;
    const int tid = threadIdx.x;
    const int w = tid >> 5;
    const int lane = tid & 31;
    const int g = lane >> 2;
    const int c = lane & 3;
    const int q0 = qt * 128;
    const int qb = w * 16;

    const uint32_t sbase = smem_u32(fsm);
    const int lm_row = lane & 15;
    const int lm_cs  = (lane >> 4) & 1;
    const int km = lane >> 3;
    const int krow = lane & 7;
    const int k_key8 = (km >> 1) << 3;
    const int k_dim8 = (km & 1) << 3;

    const int NT = qt + 1;

    auto load_kv = [&](int kt, int buf) {
        const int k0 = kt * 128;
        uint32_t kb = sbase + (uint32_t)(FL_K0 + buf * KVBUF) * 2;
        uint32_t vb = sbase + (uint32_t)(FL_V0 + buf * KVBUF) * 2;
#pragma unroll
        for (int i = 0; i < 4; i++) {
            int lin = tid + 256 * i;
            int r  = lin >> 3;
            int d8 = (lin & 7) << 3;
            uint32_t off = (uint32_t)(r * FP + d8) * 2;
            cp16(kb + off, &K[(size_t)(k0 + r) * KVDIM + kvh * HD + d8]);
            cp16(vb + off, &V[(size_t)(k0 + r) * KVDIM + kvh * HD + d8]);
        }
        CP_COMMIT();
    };

#pragma unroll
    for (int i = 0; i < 4; i++) {
        int lin = tid + 256 * i;
        int r  = lin >> 3;
        int d8 = (lin & 7) << 3;
        *(uint4*)&Qs[r * FP + d8] =
            *(const uint4*)&Q[(size_t)(q0 + r) * DIM + h * HD + d8];
    }
    load_kv(0, 0);
    __syncthreads();

    uint32_t qf[4][4];
#pragma unroll
    for (int kk = 0; kk < 4; kk++) {
        qf[kk][0] = *(uint32_t*)&Qs[(qb + g)     * FP + kk * 16 + 2 * c];
        qf[kk][1] = *(uint32_t*)&Qs[(qb + g + 8) * FP + kk * 16 + 2 * c];
        qf[kk][2] = *(uint32_t*)&Qs[(qb + g)     * FP + kk * 16 + 2 * c + 8];
        qf[kk][3] = *(uint32_t*)&Qs[(qb + g + 8) * FP + kk * 16 + 2 * c + 8];
    }

    float m0 = -1e30f, m1 = -1e30f, l0 = 0.f, l1 = 0.f;
    float oacc[8][4] = {};
    const uint32_t ones2[2] = {0x3C003C00u, 0x3C003C00u};

    for (int kt = 0; kt < NT; kt++) {
        const int buf = kt & 1;
        cp_wait<0>();
        __syncthreads();

        if (kt + 1 < NT) load_kv(kt + 1, buf ^ 1);

#pragma unroll
        for (int half = 0; half < 2; half++) {
            const int k0 = kt * 128 + half * 64;
            if (k0 > q0 + qb + 15) continue;

            const uint32_t kbyte = sbase +
                (uint32_t)(FL_K0 + buf * KVBUF + half * 64 * FP) * 2;
            const uint32_t vbyte = sbase +
                (uint32_t)(FL_V0 + buf * KVBUF + half * 64 * FP) * 2;

            float s[8][4] = {};
#pragma unroll
            for (int kk = 0; kk < 4; kk++) {
#pragma unroll
                for (int ntp = 0; ntp < 4; ntp++) {
                    uint32_t addr = kbyte +
                        (uint32_t)((ntp * 16 + k_key8 + krow) * FP +
                                   kk * 16 + k_dim8) * 2;
                    uint32_t b0, b1, b2, b3;
                    ldsm_x4(b0, b1, b2, b3, addr);
                    uint32_t blo[2] = {b0, b1}, bhi[2] = {b2, b3};
                    mma_f16(s[2 * ntp],     qf[kk], blo);
                    mma_f16(s[2 * ntp + 1], qf[kk], bhi);
                }
            }

            if (k0 + 63 > q0 + qb) {
                int r0 = q0 + qb + g, r1 = r0 + 8;
#pragma unroll
                for (int nt = 0; nt < 8; nt++) {
                    int col = k0 + nt * 8 + 2 * c;
                    if (col     > r0) s[nt][0] = -1e30f;
                    if (col + 1 > r0) s[nt][1] = -1e30f;
                    if (col     > r1) s[nt][2] = -1e30f;
                    if (col + 1 > r1) s[nt][3] = -1e30f;
                }
            }

            float mx0 = -1e30f, mx1 = -1e30f;
#pragma unroll
            for (int nt = 0; nt < 8; nt++) {
                mx0 = fmaxf(mx0, fmaxf(s[nt][0], s[nt][1]));
                mx1 = fmaxf(mx1, fmaxf(s[nt][2], s[nt][3]));
            }
            mx0 = fmaxf(mx0, __shfl_xor_sync(0xffffffffu, mx0, 1));
            mx0 = fmaxf(mx0, __shfl_xor_sync(0xffffffffu, mx0, 2));
            mx1 = fmaxf(mx1, __shfl_xor_sync(0xffffffffu, mx1, 1));
            mx1 = fmaxf(mx1, __shfl_xor_sync(0xffffffffu, mx1, 2));

            float mn0 = fmaxf(m0, mx0), mn1 = fmaxf(m1, mx1);
            float al0 = exp2f(m0 - mn0), al1 = exp2f(m1 - mn1);

            uint32_t pa[4][4];
#pragma unroll
            for (int kk = 0; kk < 4; kk++) {
                pa[kk][0] = h2exp2(s[2 * kk][0] - mn0,     s[2 * kk][1] - mn0);
                pa[kk][1] = h2exp2(s[2 * kk][2] - mn1,     s[2 * kk][3] - mn1);
                pa[kk][2] = h2exp2(s[2 * kk + 1][0] - mn0, s[2 * kk + 1][1] - mn0);
                pa[kk][3] = h2exp2(s[2 * kk + 1][2] - mn1, s[2 * kk + 1][3] - mn1);
            }

            float sacc[4] = {};
#pragma unroll
            for (int kk = 0; kk < 4; kk++)
                mma_f16(sacc, pa[kk], ones2);

            l0 = l0 * al0 + sacc[0];  m0 = mn0;
            l1 = l1 * al1 + sacc[2];  m1 = mn1;
#pragma unroll
            for (int nt = 0; nt < 8; nt++) {
                oacc[nt][0] *= al0; oacc[nt][1] *= al0;
                oacc[nt][2] *= al1; oacc[nt][3] *= al1;
            }

#pragma unroll
            for (int kk = 0; kk < 4; kk++) {
#pragma unroll
                for (int ntp = 0; ntp < 4; ntp++) {
                    uint32_t addr = vbyte +
                        (uint32_t)(kk * 16 + lm_row) * (FP * 2) +
                        (uint32_t)(16 * ntp + 8 * lm_cs) * 2;
                    uint32_t b0, b1, b2, b3;
                    ldsm_x4_trans(b0, b1, b2, b3, addr);
                    uint32_t blo[2] = {b0, b1}, bhi[2] = {b2, b3};
                    mma_f16(oacc[2 * ntp],     pa[kk], blo);
                    mma_f16(oacc[2 * ntp + 1], pa[kk], bhi);
                }
            }
        }
    }

    float inv0 = 1.f / l0, inv1 = 1.f / l1;
    int r0 = q0 + qb + g;
#pragma unroll
    for (int nt = 0; nt < 8; nt++) {
        int col = h * HD + nt * 8 + 2 * c;
        *(uint32_t*)&O[(size_t)r0 * DIM + col] =
            pack_h2(oacc[nt][0] * inv0, oacc[nt][1] * inv0);
        *(uint32_t*)&O[(size_t)(r0 + 8) * DIM + col] =
            pack_h2(oacc[nt][2] * inv1, oacc[nt][3] * inv1);
    }
}

// ---------------------------------------------------------------------------
// Launch
// ---------------------------------------------------------------------------
extern "C" void kernel_launch(void* const* d_in, const int* in_sizes, int n_in,
                              void* d_out, int out_size) {
    const float* x  = (const float*)d_in[0];
    const float* fc = (const float*)d_in[1];
    const float* fs = (const float*)d_in[2];
    const float* wq = (const float*)d_in[3];
    const float* wk = (const float*)d_in[4];
    const float* wv = (const float*)d_in[5];
    const float* wo = (const float*)d_in[6];
    float* out = (float*)d_out;

    static __half *pq = nullptr, *pk, *pv, *pa, *px, *pwq, *pwk, *pwv, *pwo;
    if (!pq) {
        cudaGetSymbolAddress((void**)&pq,  g_qh);
        cudaGetSymbolAddress((void**)&pk,  g_kh);
        cudaGetSymbolAddress((void**)&pv,  g_vh);
        cudaGetSymbolAddress((void**)&pa,  g_ah);
        cudaGetSymbolAddress((void**)&px,  g_xh);
        cudaGetSymbolAddress((void**)&pwq, g_wqh);
        cudaGetSymbolAddress((void**)&pwk, g_wkh);
        cudaGetSymbolAddress((void**)&pwv, g_wvh);
        cudaGetSymbolAddress((void**)&pwo, g_woh);
        cudaFuncSetAttribute(flash_f16,
                             cudaFuncAttributeMaxDynamicSharedMemorySize,
                             FLASH_SMEM);
        cudaFuncSetAttribute(gemm_qkv,
                             cudaFuncAttributeMaxDynamicSharedMemorySize,
                             GEMM_SMEM);
        cudaFuncSetAttribute(gemm_o,
                             cudaFuncAttributeMaxDynamicSharedMemorySize,
                             GEMM_SMEM);
    }

    cvt_all<<<(N4_TOT + 255) / 256, 256>>>(
        (const float4*)x,  (uint2*)px,
        (const float4*)wq, (uint2*)pwq,
        (const float4*)wk, (uint2*)pwk,
        (const float4*)wv, (uint2*)pwv,
        (const float4*)wo, (uint2*)pwo);

    dim3 blk(256);
    gemm_qkv<<<dim3((DIM + 2 * KVDIM) / 64, SEQ / 128), blk, GEMM_SMEM>>>(
        px, pwq, pwk, pwv, pq, pk, pv, fc, fs);

    flash_f16<<<dim3(SEQ / 128, NHEADS), blk, FLASH_SMEM>>>(pq, pk, pv, pa);

    gemm_o<<<dim3(DIM / 64, SEQ / 128), blk, GEMM_SMEM>>>(pa, pwo, out);
}